// round 11
// baseline (speedup 1.0000x reference)
#include <cuda_runtime.h>
#include <cstddef>

#define DEVF __device__ __forceinline__
typedef unsigned long long ull;

// ---------------- scratch (device globals; no allocations allowed) ----------
__device__ float g_q  [3200 * 512];
__device__ float g_k  [12288 * 512];
__device__ float g_v  [12288 * 512];
__device__ float g_ctx[3200 * 512];
__device__ float g_x1 [3200 * 512];
__device__ float g_x2 [3200 * 512];
__device__ float g_tmp[3200 * 512];
__device__ float g_yt [3200 * 512];

// LSTM wavefront buffers: Y[l][t][k][b], l = 0..32, t<512, k<25, b<128
#define YSTRIDE 1638400   // 512*25*128
__device__ float g_Y[33ull * YSTRIDE];
__device__ int   g_flags[33 * 4 * 32];   // (layer,chunk) progress, 128B padded

// ---------------- activations ------------------------------------------------
DEVF float tanh_fast(float x) {
    float y; asm("tanh.approx.f32 %0, %1;" : "=f"(y) : "f"(x)); return y;
}
DEVF float sig_fast(float x) { return fmaf(tanh_fast(0.5f * x), 0.5f, 0.5f); }

// ---------------- tf32 helpers -----------------------------------------------
DEVF unsigned totf(float x) {
    unsigned r; asm("cvt.rna.tf32.f32 %0, %1;" : "=r"(r) : "f"(x)); return r;
}
DEVF void mma_tf32(float* c, const unsigned* a, unsigned b0, unsigned b1) {
    asm("mma.sync.aligned.m16n8k8.row.col.f32.tf32.tf32.f32 "
        "{%0,%1,%2,%3}, {%4,%5,%6,%7}, {%8,%9}, {%0,%1,%2,%3};"
        : "+f"(c[0]), "+f"(c[1]), "+f"(c[2]), "+f"(c[3])
        : "r"(a[0]), "r"(a[1]), "r"(a[2]), "r"(a[3]), "r"(b0), "r"(b1));
}

DEVF void cpasync16(unsigned dst, const void* src) {
    asm volatile("cp.async.cg.shared.global [%0], [%1], 16;" :: "r"(dst), "l"(src));
}
DEVF void cp_commit() { asm volatile("cp.async.commit_group;"); }
DEVF void cp_wait2()  { asm volatile("cp.async.wait_group 2;"); }

// ---------------- tf32 tensor-core GEMM, cp.async 4-stage, BK=16 -------------
// C[.,512] = A[.,512] @ W (+bias)(+res). TRANSW: W stored [N,K] else [K,N].
#define ASTR 20
#define AWRD (64 * ASTR)       // 1280
#define BWRD 1296              // >= max(16*72, 64*20)
template<bool TRANSW>
DEVF void gemm_tc_core(const float* __restrict__ A, const float* __restrict__ W,
                       const float* __restrict__ bias, const float* __restrict__ res,
                       float* __restrict__ C)
{
    __shared__ __align__(16) float As[4][AWRD];
    __shared__ __align__(16) float Bsm[4][BWRD];

    int tid = threadIdx.x;
    int bm = blockIdx.x * 64, bn = blockIdx.y * 64;
    int lane = tid & 31, wid = tid >> 5;
    int wm = wid & 1, wn = wid >> 1;
    int g = lane >> 2, tg = lane & 3;

    float acc[2][4][4];
    #pragma unroll
    for (int i = 0; i < 2; i++)
        #pragma unroll
        for (int j = 0; j < 4; j++)
            #pragma unroll
            for (int q = 0; q < 4; q++) acc[i][j][q] = 0.f;

    int ar = tid >> 1, ac = (tid & 1) * 8;
    const float* Asrc = A + (size_t)(bm + ar) * 512 + ac;
    int kk = tid >> 3, nn = (tid & 7) * 8;
    int nr = tid >> 1, kc = (tid & 1) * 8;
    const float* Bsrc = TRANSW ? (W + (size_t)(bn + nr) * 512 + kc)
                               : (W + (size_t)kk * 512 + bn + nn);

    unsigned asb = (unsigned)__cvta_generic_to_shared(&As[0][0]);
    unsigned bsb = (unsigned)__cvta_generic_to_shared(&Bsm[0][0]);
    unsigned adst = asb + (ar * ASTR + ac) * 4;
    unsigned bdst = bsb + (TRANSW ? (nr * ASTR + kc) : (kk * 72 + nn)) * 4;

    #pragma unroll
    for (int p = 0; p < 3; p++) {
        int k0 = p * 16;
        cpasync16(adst + p * AWRD * 4, Asrc + k0);
        cpasync16(adst + p * AWRD * 4 + 16, Asrc + k0 + 4);
        const float* bs = TRANSW ? (Bsrc + k0) : (Bsrc + (size_t)k0 * 512);
        cpasync16(bdst + p * BWRD * 4, bs);
        cpasync16(bdst + p * BWRD * 4 + 16, bs + 4);
        cp_commit();
    }

    int am0 = wm * 32 + g;

    for (int it = 0; it < 32; it++) {
        int st = it & 3;
        cp_wait2();
        __syncthreads();
        if (it + 3 < 32) {
            int tl = it + 3, ns = tl & 3;
            int k0 = tl * 16;
            cpasync16(adst + ns * AWRD * 4, Asrc + k0);
            cpasync16(adst + ns * AWRD * 4 + 16, Asrc + k0 + 4);
            const float* bs = TRANSW ? (Bsrc + k0) : (Bsrc + (size_t)k0 * 512);
            cpasync16(bdst + ns * BWRD * 4, bs);
            cpasync16(bdst + ns * BWRD * 4 + 16, bs + 4);
        }
        cp_commit();

        const unsigned* Au = (const unsigned*)As[st];
        const unsigned* Bu = (const unsigned*)Bsm[st];
        #pragma unroll
        for (int ks = 0; ks < 2; ks++) {
            int klo = ks * 8 + tg;
            unsigned afr[2][4];
            #pragma unroll
            for (int mf = 0; mf < 2; mf++) {
                int m = am0 + mf * 16;
                afr[mf][0] = Au[m * ASTR + klo];
                afr[mf][1] = Au[(m + 8) * ASTR + klo];
                afr[mf][2] = Au[m * ASTR + klo + 4];
                afr[mf][3] = Au[(m + 8) * ASTR + klo + 4];
            }
            #pragma unroll
            for (int nf = 0; nf < 4; nf++) {
                int col = wn * 32 + nf * 8 + g;
                unsigned b0, b1;
                if (!TRANSW) {
                    b0 = Bu[klo * 72 + col];
                    b1 = Bu[(klo + 4) * 72 + col];
                } else {
                    b0 = Bu[col * ASTR + klo];
                    b1 = Bu[col * ASTR + klo + 4];
                }
                mma_tf32(acc[0][nf], afr[0], b0, b1);
                mma_tf32(acc[1][nf], afr[1], b0, b1);
            }
        }
        __syncthreads();
    }

    #pragma unroll
    for (int nf = 0; nf < 4; nf++) {
        int col = bn + wn * 32 + nf * 8 + 2 * tg;
        float2 bv = *(const float2*)(bias + col);
        #pragma unroll
        for (int mf = 0; mf < 2; mf++) {
            int row = bm + wm * 32 + mf * 16 + g;
            float2 v0 = make_float2(acc[mf][nf][0] + bv.x, acc[mf][nf][1] + bv.y);
            float2 v1 = make_float2(acc[mf][nf][2] + bv.x, acc[mf][nf][3] + bv.y);
            if (res) {
                float2 r0 = *(const float2*)(res + (size_t)row * 512 + col);
                float2 r1 = *(const float2*)(res + (size_t)(row + 8) * 512 + col);
                v0.x += r0.x; v0.y += r0.y; v1.x += r1.x; v1.y += r1.y;
            }
            *(float2*)(C + (size_t)row * 512 + col) = v0;
            *(float2*)(C + (size_t)(row + 8) * 512 + col) = v1;
        }
    }
}

struct GemmSet {
    const float* W[3];
    const float* b[3];
    const float* r[3];
    float*       C[3];
};

template<bool TRANSW>
__global__ void __launch_bounds__(128, 5) gemm_tc_kernel(const float* __restrict__ A, GemmSet s) {
    int z = blockIdx.z;
    gemm_tc_core<TRANSW>(A, s.W[z], s.b[z], s.r[z], s.C[z]);
}

// ---------------- attention core: one block per (b, h), 256 threads ---------
template<int S>
__global__ void __launch_bounds__(256) attn_kernel(
    const float* __restrict__ Q, const float* __restrict__ Kp,
    const float* __restrict__ Vp, float* __restrict__ O)
{
    __shared__ float qs[25 * 64];
    __shared__ __align__(16) float kv[96 * 64];
    __shared__ float sc[25 * S];
    int b = blockIdx.x >> 3, h = blockIdx.x & 7;
    int tid = threadIdx.x;
    const float scale = 0.125f;
    size_t qbase = (size_t)b * 25 * 512 + h * 64;
    size_t kbase = (size_t)b * S  * 512 + h * 64;

    for (int i = tid; i < 25 * 64; i += 256) qs[i] = Q[qbase + (size_t)(i >> 6) * 512 + (i & 63)];
    for (int i = tid; i < S  * 64; i += 256) kv[i] = Kp[kbase + (size_t)(i >> 6) * 512 + (i & 63)];
    __syncthreads();

    for (int i = tid; i < 25 * S; i += 256) {
        int l = i / S, s = i - l * S;
        float acc = 0.f;
        #pragma unroll
        for (int e4 = 0; e4 < 16; e4++) {
            float4 q4 = *(const float4*)&qs[l * 64 + e4 * 4];
            float4 k4 = *(const float4*)&kv[s * 64 + e4 * 4];
            acc += q4.x * k4.x + q4.y * k4.y + q4.z * k4.z + q4.w * k4.w;
        }
        sc[i] = acc * scale;
    }
    __syncthreads();

    int warp = tid >> 5, lane = tid & 31;
    for (int l = warp; l < 25; l += 8) {
        float mx = -1e30f;
        for (int s = lane; s < S; s += 32) mx = fmaxf(mx, sc[l * S + s]);
        #pragma unroll
        for (int o = 16; o; o >>= 1) mx = fmaxf(mx, __shfl_xor_sync(~0u, mx, o));
        float sum = 0.f;
        for (int s = lane; s < S; s += 32) {
            float e = __expf(sc[l * S + s] - mx);
            sc[l * S + s] = e; sum += e;
        }
        #pragma unroll
        for (int o = 16; o; o >>= 1) sum += __shfl_xor_sync(~0u, sum, o);
        float inv = __fdividef(1.f, sum);
        for (int s = lane; s < S; s += 32) sc[l * S + s] *= inv;
    }
    __syncthreads();

    for (int i = tid; i < S * 64; i += 256) kv[i] = Vp[kbase + (size_t)(i >> 6) * 512 + (i & 63)];
    __syncthreads();

    for (int i = tid; i < 25 * 16; i += 256) {
        int l = i >> 4, e4 = (i & 15) * 4;
        float4 acc = make_float4(0.f, 0.f, 0.f, 0.f);
        const float* scl = &sc[l * S];
        #pragma unroll 4
        for (int s = 0; s < S; s++) {
            float w = scl[s];
            float4 v4 = *(const float4*)&kv[s * 64 + e4];
            acc.x += w * v4.x; acc.y += w * v4.y;
            acc.z += w * v4.z; acc.w += w * v4.w;
        }
        *(float4*)(&O[qbase + (size_t)l * 512 + e4]) = acc;
    }
}

// ---------------- LayerNorm over rows of 512 (warp per row) ------------------
__global__ void __launch_bounds__(256) ln_kernel(
    const float* __restrict__ in, const float* __restrict__ g,
    const float* __restrict__ bb, float* __restrict__ out, int M)
{
    int row = blockIdx.x * 8 + (threadIdx.x >> 5);
    int lane = threadIdx.x & 31;
    if (row >= M) return;
    const float* p = in + (size_t)row * 512;
    float v[16];
    float s = 0.f, s2 = 0.f;
    #pragma unroll
    for (int i = 0; i < 16; i++) {
        v[i] = p[lane + 32 * i];
        s += v[i]; s2 += v[i] * v[i];
    }
    #pragma unroll
    for (int o = 16; o; o >>= 1) {
        s  += __shfl_xor_sync(~0u, s,  o);
        s2 += __shfl_xor_sync(~0u, s2, o);
    }
    float mean = s * (1.f / 512.f);
    float var  = s2 * (1.f / 512.f) - mean * mean;
    float rstd = rsqrtf(var + 1e-5f);
    float* q = out + (size_t)row * 512;
    #pragma unroll
    for (int i = 0; i < 16; i++) {
        int d = lane + 32 * i;
        q[d] = (v[i] - mean) * rstd * g[d] + bb[d];
    }
}

// ---------------- tiled transposes -------------------------------------------
__global__ void transpose_in_kernel(const float* __restrict__ in, float* __restrict__ out) {
    __shared__ float tile[32][33];
    int tx = threadIdx.x, ty = threadIdx.y;
    int t0 = blockIdx.x * 32, b0 = blockIdx.y * 32, k = blockIdx.z;
    #pragma unroll
    for (int i = 0; i < 4; i++)
        tile[ty + 8 * i][tx] = in[(size_t)(b0 + ty + 8 * i) * 12800 + k * 512 + t0 + tx];
    __syncthreads();
    #pragma unroll
    for (int i = 0; i < 4; i++)
        out[(size_t)(t0 + ty + 8 * i) * 3200 + k * 128 + b0 + tx] = tile[tx][ty + 8 * i];
}
__global__ void transpose_out_kernel(const float* __restrict__ in, float* __restrict__ out) {
    __shared__ float tile[32][33];
    int tx = threadIdx.x, ty = threadIdx.y;
    int c0 = blockIdx.x * 32, b0 = blockIdx.y * 32, l = blockIdx.z;
    #pragma unroll
    for (int i = 0; i < 4; i++)
        tile[ty + 8 * i][tx] = in[(size_t)(c0 + ty + 8 * i) * 3200 + l * 128 + b0 + tx];
    __syncthreads();
    #pragma unroll
    for (int i = 0; i < 4; i++)
        out[(size_t)((b0 + ty + 8 * i) * 25 + l) * 512 + c0 + tx] = tile[tx][ty + 8 * i];
}

__global__ void zero_flags_kernel() {
    int i = blockIdx.x * 256 + threadIdx.x;
    if (i < 33 * 4 * 32) g_flags[i] = 0;
}

DEVF void spinwait(const int* p, int need) {
    int v;
    do {
        asm volatile("ld.acquire.gpu.global.b32 %0, [%1];" : "=r"(v) : "l"(p) : "memory");
    } while (v < need);
}

// ---------------- tensor-core LSTM wavefront, lag-3 pipeline -----------------
// 128 blocks = 32 layers x 4 chunks(32 batches). 160 threads: warps 0-3 compute,
// warp 4 = IO. B = [x(25); h(25); pad] tf32, 4-slot rotation:
//   step t reads slot t&3 (x_t written 3 steps ago, h_{t-1} written 1 step ago),
//   h_t -> slot (t+1)&3, x_{t+3} prefetched -> slot (t+3)&3 (upstream finished
//   it 2 steps before we need it => flag poll hits first try, handoff hidden).
#define BROWS 56
#define BSTR  40
__global__ void __launch_bounds__(160, 1) lstm_wave_kernel(
    const float* __restrict__ Wih, const float* __restrict__ Whh,
    const float* __restrict__ bih, const float* __restrict__ bhh)
{
    __shared__ __align__(16) unsigned Bsm[4][BROWS][BSTR];

    int layer = blockIdx.x & 31;
    int chunk = blockIdx.x >> 5;
    int b0 = chunk * 32;
    const float* in  = g_Y + (size_t)layer * YSTRIDE;
    float* outp      = g_Y + (size_t)(layer + 1) * YSTRIDE;
    const int* inflag = g_flags + (layer * 4 + chunk) * 32;
    int* outflag      = g_flags + ((layer + 1) * 4 + chunk) * 32;

    int tid = threadIdx.x;
    int warp = tid >> 5, lane = tid & 31;
    int g = lane >> 2, tg = lane & 3;

    for (int i = tid; i < 4 * BROWS * BSTR; i += 160) ((unsigned*)Bsm)[i] = 0;

    unsigned afr[2][7][4];
    float bias_i = 0.f, bias_f = 0.f, bias_g = 0.f, bias_o = 0.f;
    int u = warp * 8 + g;
    bool isComp = (warp < 4);
    bool valid = isComp && (u < 25);
    if (isComp) {
        const float* WI = Wih + (size_t)layer * 2500;
        const float* WH = Whh + (size_t)layer * 2500;
        #pragma unroll
        for (int T = 0; T < 2; T++) {
            int rowA = (T == 0 ? 0 : 50) + u;
            int rowB = (T == 0 ? 25 : 75) + u;
            #pragma unroll
            for (int ks = 0; ks < 7; ks++) {
                #pragma unroll
                for (int q = 0; q < 4; q++) {
                    int k = ks * 8 + tg + (q >= 2 ? 4 : 0);
                    int row = (q & 1) ? rowB : rowA;
                    float w = 0.f;
                    if (valid) {
                        if (k < 25)      w = WI[row * 25 + k];
                        else if (k < 50) w = WH[row * 25 + (k - 25)];
                    }
                    afr[T][ks][q] = totf(w);
                }
            }
        }
        if (valid) {
            bias_i = bih[layer * 100 + u]      + bhh[layer * 100 + u];
            bias_f = bih[layer * 100 + 25 + u] + bhh[layer * 100 + 25 + u];
            bias_g = bih[layer * 100 + 50 + u] + bhh[layer * 100 + 50 + u];
            bias_o = bih[layer * 100 + 75 + u] + bhh[layer * 100 + 75 + u];
        }
    }
    float c[8];
    #pragma unroll
    for (int i = 0; i < 8; i++) c[i] = 0.f;
    __syncthreads();

    // prologue: x_0 -> slot0, x_1 -> slot1, x_2 -> slot2 (upstream must be 3 ahead)
    if (warp == 4) {
        if (layer > 0 && lane == 0) spinwait(inflag, 3);
        __syncwarp();
        #pragma unroll
        for (int p = 0; p < 3; p++) {
            const float* src = in + (size_t)p * 3200 + b0;
            #pragma unroll
            for (int k = 0; k < 25; k++)
                Bsm[p][k][lane] = totf(src[k * 128 + lane]);
        }
    }
    __syncthreads();

    for (int t = 0; t < 512; t++) {
        int s = t & 3;
        if (isComp) {
            float acc0[4][4], acc1[4][4];
            #pragma unroll
            for (int nf = 0; nf < 4; nf++) {
                acc0[nf][0] = bias_i; acc0[nf][1] = bias_i;
                acc0[nf][2] = bias_f; acc0[nf][3] = bias_f;
                acc1[nf][0] = bias_g; acc1[nf][1] = bias_g;
                acc1[nf][2] = bias_o; acc1[nf][3] = bias_o;
            }
            const unsigned* Bp = &Bsm[s][0][0];
            #pragma unroll
            for (int ks = 0; ks < 7; ks++) {
                int r0 = (ks * 8 + tg) * BSTR;
                #pragma unroll
                for (int nf = 0; nf < 4; nf++) {
                    unsigned b0v = Bp[r0 + nf * 8 + g];
                    unsigned b1v = Bp[r0 + 4 * BSTR + nf * 8 + g];
                    mma_tf32(acc0[nf], afr[0][ks], b0v, b1v);
                    mma_tf32(acc1[nf], afr[1][ks], b0v, b1v);
                }
            }
            unsigned* Bn = &Bsm[(t + 1) & 3][0][0];
            #pragma unroll
            for (int nf = 0; nf < 4; nf++) {
                float i0 = sig_fast(acc0[nf][0]),  i1 = sig_fast(acc0[nf][1]);
                float f0 = sig_fast(acc0[nf][2]),  f1 = sig_fast(acc0[nf][3]);
                float q0 = tanh_fast(acc1[nf][0]), q1 = tanh_fast(acc1[nf][1]);
                float o0 = sig_fast(acc1[nf][2]),  o1 = sig_fast(acc1[nf][3]);
                c[2 * nf]     = f0 * c[2 * nf]     + i0 * q0;
                c[2 * nf + 1] = f1 * c[2 * nf + 1] + i1 * q1;
                float h0 = o0 * tanh_fast(c[2 * nf]);
                float h1 = o1 * tanh_fast(c[2 * nf + 1]);
                if (valid) {
                    uint2 hp = make_uint2(totf(h0), totf(h1));
                    *(uint2*)&Bn[(25 + u) * BSTR + nf * 8 + 2 * tg] = hp;
                    *(float2*)(outp + (size_t)t * 3200 + u * 128 + b0 + nf * 8 + 2 * tg)
                        = make_float2(h0, h1);
                }
            }
        } else {
            if (t < 509) {
                if (layer > 0 && lane == 0) spinwait(inflag, t + 4);
                __syncwarp();
                const float* src = in + (size_t)(t + 3) * 3200 + b0;
                unsigned* Bx = &Bsm[(t + 3) & 3][0][0];
                #pragma unroll
                for (int k = 0; k < 25; k++)
                    Bx[k * BSTR + lane] = totf(src[k * 128 + lane]);
            }
        }
        __syncthreads();
        if (tid == 0) {
            int nv = t + 1;
            asm volatile("st.release.gpu.global.b32 [%0], %1;" :: "l"(outflag), "r"(nv) : "memory");
        }
    }
}

// ---------------- launcher ---------------------------------------------------
extern "C" void kernel_launch(void* const* d_in, const int* in_sizes, int n_in,
                              void* d_out, int out_size)
{
    const float* x     = (const float*)d_in[0];
    const float* cross = (const float*)d_in[1];
    const float* Wq_s = (const float*)d_in[2];  const float* bq_s = (const float*)d_in[3];
    const float* Wk_s = (const float*)d_in[4];  const float* bk_s = (const float*)d_in[5];
    const float* Wv_s = (const float*)d_in[6];  const float* bv_s = (const float*)d_in[7];
    const float* Wo_s = (const float*)d_in[8];  const float* bo_s = (const float*)d_in[9];
    const float* Wq_c = (const float*)d_in[10]; const float* bq_c = (const float*)d_in[11];
    const float* Wk_c = (const float*)d_in[12]; const float* bk_c = (const float*)d_in[13];
    const float* Wv_c = (const float*)d_in[14]; const float* bv_c = (const float*)d_in[15];
    const float* Wo_c = (const float*)d_in[16]; const float* bo_c = (const float*)d_in[17];
    const float* g1 = (const float*)d_in[18]; const float* b1 = (const float*)d_in[19];
    const float* g2 = (const float*)d_in[20]; const float* b2 = (const float*)d_in[21];
    const float* g3 = (const float*)d_in[22]; const float* b3 = (const float*)d_in[23];
    const float* W_ih = (const float*)d_in[24];
    const float* W_hh = (const float*)d_in[25];
    const float* b_ih = (const float*)d_in[26];
    const float* b_hh = (const float*)d_in[27];
    const float* Wc = (const float*)d_in[28]; const float* bc = (const float*)d_in[29];
    float* out = (float*)d_out;

    float *gq, *gk, *gv, *gctx, *gx1, *gx2, *gtmp, *gyt, *gY;
    cudaGetSymbolAddress((void**)&gq,   g_q);
    cudaGetSymbolAddress((void**)&gk,   g_k);
    cudaGetSymbolAddress((void**)&gv,   g_v);
    cudaGetSymbolAddress((void**)&gctx, g_ctx);
    cudaGetSymbolAddress((void**)&gx1,  g_x1);
    cudaGetSymbolAddress((void**)&gx2,  g_x2);
    cudaGetSymbolAddress((void**)&gtmp, g_tmp);
    cudaGetSymbolAddress((void**)&gyt,  g_yt);
    cudaGetSymbolAddress((void**)&gY,   g_Y);

    const int M1 = 3200;    // B*L
    zero_flags_kernel<<<17, 256>>>();

    // ---- self attention ----
    {
        GemmSet s = {{Wq_s, Wk_s, Wv_s}, {bq_s, bk_s, bv_s},
                     {nullptr, nullptr, nullptr}, {gq, gk, gv}};
        gemm_tc_kernel<false><<<dim3(50, 8, 3), 128>>>(x, s);
    }
    attn_kernel<25><<<128 * 8, 256>>>(gq, gk, gv, gctx);
    {
        GemmSet s = {{Wo_s, nullptr, nullptr}, {bo_s, nullptr, nullptr},
                     {x, nullptr, nullptr}, {gtmp, nullptr, nullptr}};
        gemm_tc_kernel<false><<<dim3(50, 8, 1), 128>>>(gctx, s);
    }
    ln_kernel<<<M1 / 8, 256>>>(gtmp, g1, b1, gx1, M1);

    // ---- cross attention ----
    {
        GemmSet s = {{Wq_c, nullptr, nullptr}, {bq_c, nullptr, nullptr},
                     {nullptr, nullptr, nullptr}, {gq, nullptr, nullptr}};
        gemm_tc_kernel<false><<<dim3(50, 8, 1), 128>>>(gx1, s);
    }
    {
        GemmSet s = {{Wk_c, Wv_c, nullptr}, {bk_c, bv_c, nullptr},
                     {nullptr, nullptr, nullptr}, {gk, gv, nullptr}};
        gemm_tc_kernel<false><<<dim3(192, 8, 2), 128>>>(cross, s);
    }
    attn_kernel<96><<<128 * 8, 256>>>(gq, gk, gv, gctx);
    {
        GemmSet s = {{Wo_c, nullptr, nullptr}, {bo_c, nullptr, nullptr},
                     {gx1, nullptr, nullptr}, {gtmp, nullptr, nullptr}};
        gemm_tc_kernel<false><<<dim3(50, 8, 1), 128>>>(gctx, s);
    }
    ln_kernel<<<M1 / 8, 256>>>(gtmp, g2, b2, gx2, M1);

    // ---- LSTM wavefront over feature axis ----
    transpose_in_kernel<<<dim3(16, 4, 25), dim3(32, 8)>>>(gx2, gY);
    lstm_wave_kernel<<<128, 160>>>(W_ih, W_hh, b_ih, b_hh);

    // ---- pointwise conv + residual + final LN ----
    transpose_out_kernel<<<dim3(16, 4, 25), dim3(32, 8)>>>(gY + 32ull * YSTRIDE, gyt);
    {
        GemmSet s = {{Wc, nullptr, nullptr}, {bc, nullptr, nullptr},
                     {gx2, nullptr, nullptr}, {gtmp, nullptr, nullptr}};
        gemm_tc_kernel<true><<<dim3(50, 8, 1), 128>>>(gyt, s);
    }
    ln_kernel<<<M1 / 8, 256>>>(gtmp, g3, b3, out, M1);
}

// round 12
// speedup vs baseline: 1.0666x; 1.0666x over previous
#include <cuda_runtime.h>
#include <cstddef>

#define DEVF __device__ __forceinline__
typedef unsigned long long ull;

// ---------------- scratch (device globals; no allocations allowed) ----------
__device__ float g_q  [3200 * 512];
__device__ float g_k  [12288 * 512];
__device__ float g_v  [12288 * 512];
__device__ float g_ctx[3200 * 512];
__device__ float g_x1 [3200 * 512];
__device__ float g_x2 [3200 * 512];
__device__ float g_tmp[3200 * 512];
__device__ float g_yt [3200 * 512];

// LSTM wavefront buffers: Y[l][t][k][b], l = 0..32, t<512, k<25, b<128
#define YSTRIDE 1638400   // 512*25*128
__device__ float g_Y[33ull * YSTRIDE];
__device__ int   g_flags[33 * 4 * 32];   // (layer,chunk) progress, 128B padded

// ---------------- activations ------------------------------------------------
DEVF float tanh_fast(float x) {
    float y; asm("tanh.approx.f32 %0, %1;" : "=f"(y) : "f"(x)); return y;
}
DEVF float sig_fast(float x) { return fmaf(tanh_fast(0.5f * x), 0.5f, 0.5f); }

// ---------------- tf32 helpers -----------------------------------------------
DEVF unsigned totf(float x) {
    unsigned r; asm("cvt.rna.tf32.f32 %0, %1;" : "=r"(r) : "f"(x)); return r;
}
DEVF void mma_tf32(float* c, const unsigned* a, unsigned b0, unsigned b1) {
    asm("mma.sync.aligned.m16n8k8.row.col.f32.tf32.tf32.f32 "
        "{%0,%1,%2,%3}, {%4,%5,%6,%7}, {%8,%9}, {%0,%1,%2,%3};"
        : "+f"(c[0]), "+f"(c[1]), "+f"(c[2]), "+f"(c[3])
        : "r"(a[0]), "r"(a[1]), "r"(a[2]), "r"(a[3]), "r"(b0), "r"(b1));
}

DEVF void cpasync16(unsigned dst, const void* src) {
    asm volatile("cp.async.cg.shared.global [%0], [%1], 16;" :: "r"(dst), "l"(src));
}
DEVF void cpasync4(unsigned dst, const void* src) {
    asm volatile("cp.async.ca.shared.global [%0], [%1], 4;" :: "r"(dst), "l"(src));
}
DEVF void cp_commit() { asm volatile("cp.async.commit_group;"); }
DEVF void cp_wait2()  { asm volatile("cp.async.wait_group 2;"); }
DEVF void cp_wait1()  { asm volatile("cp.async.wait_group 1;"); }
DEVF void cp_wait0()  { asm volatile("cp.async.wait_group 0;"); }

// ---------------- tf32 tensor-core GEMM, cp.async 4-stage, BK=16 -------------
// C[.,512] = A[.,512] @ W (+bias)(+res). TRANSW: W stored [N,K] else [K,N].
#define ASTR 20
#define AWRD (64 * ASTR)       // 1280
#define BWRD 1296              // >= max(16*72, 64*20)
template<bool TRANSW>
DEVF void gemm_tc_core(const float* __restrict__ A, const float* __restrict__ W,
                       const float* __restrict__ bias, const float* __restrict__ res,
                       float* __restrict__ C)
{
    __shared__ __align__(16) float As[4][AWRD];
    __shared__ __align__(16) float Bsm[4][BWRD];

    int tid = threadIdx.x;
    int bm = blockIdx.x * 64, bn = blockIdx.y * 64;
    int lane = tid & 31, wid = tid >> 5;
    int wm = wid & 1, wn = wid >> 1;
    int g = lane >> 2, tg = lane & 3;

    float acc[2][4][4];
    #pragma unroll
    for (int i = 0; i < 2; i++)
        #pragma unroll
        for (int j = 0; j < 4; j++)
            #pragma unroll
            for (int q = 0; q < 4; q++) acc[i][j][q] = 0.f;

    int ar = tid >> 1, ac = (tid & 1) * 8;
    const float* Asrc = A + (size_t)(bm + ar) * 512 + ac;
    int kk = tid >> 3, nn = (tid & 7) * 8;
    int nr = tid >> 1, kc = (tid & 1) * 8;
    const float* Bsrc = TRANSW ? (W + (size_t)(bn + nr) * 512 + kc)
                               : (W + (size_t)kk * 512 + bn + nn);

    unsigned asb = (unsigned)__cvta_generic_to_shared(&As[0][0]);
    unsigned bsb = (unsigned)__cvta_generic_to_shared(&Bsm[0][0]);
    unsigned adst = asb + (ar * ASTR + ac) * 4;
    unsigned bdst = bsb + (TRANSW ? (nr * ASTR + kc) : (kk * 72 + nn)) * 4;

    #pragma unroll
    for (int p = 0; p < 3; p++) {
        int k0 = p * 16;
        cpasync16(adst + p * AWRD * 4, Asrc + k0);
        cpasync16(adst + p * AWRD * 4 + 16, Asrc + k0 + 4);
        const float* bs = TRANSW ? (Bsrc + k0) : (Bsrc + (size_t)k0 * 512);
        cpasync16(bdst + p * BWRD * 4, bs);
        cpasync16(bdst + p * BWRD * 4 + 16, bs + 4);
        cp_commit();
    }

    int am0 = wm * 32 + g;

    for (int it = 0; it < 32; it++) {
        int st = it & 3;
        cp_wait2();
        __syncthreads();
        if (it + 3 < 32) {
            int tl = it + 3, ns = tl & 3;
            int k0 = tl * 16;
            cpasync16(adst + ns * AWRD * 4, Asrc + k0);
            cpasync16(adst + ns * AWRD * 4 + 16, Asrc + k0 + 4);
            const float* bs = TRANSW ? (Bsrc + k0) : (Bsrc + (size_t)k0 * 512);
            cpasync16(bdst + ns * BWRD * 4, bs);
            cpasync16(bdst + ns * BWRD * 4 + 16, bs + 4);
        }
        cp_commit();

        const unsigned* Au = (const unsigned*)As[st];
        const unsigned* Bu = (const unsigned*)Bsm[st];
        #pragma unroll
        for (int ks = 0; ks < 2; ks++) {
            int klo = ks * 8 + tg;
            unsigned afr[2][4];
            #pragma unroll
            for (int mf = 0; mf < 2; mf++) {
                int m = am0 + mf * 16;
                afr[mf][0] = Au[m * ASTR + klo];
                afr[mf][1] = Au[(m + 8) * ASTR + klo];
                afr[mf][2] = Au[m * ASTR + klo + 4];
                afr[mf][3] = Au[(m + 8) * ASTR + klo + 4];
            }
            #pragma unroll
            for (int nf = 0; nf < 4; nf++) {
                int col = wn * 32 + nf * 8 + g;
                unsigned b0, b1;
                if (!TRANSW) {
                    b0 = Bu[klo * 72 + col];
                    b1 = Bu[(klo + 4) * 72 + col];
                } else {
                    b0 = Bu[col * ASTR + klo];
                    b1 = Bu[col * ASTR + klo + 4];
                }
                mma_tf32(acc[0][nf], afr[0], b0, b1);
                mma_tf32(acc[1][nf], afr[1], b0, b1);
            }
        }
        __syncthreads();
    }

    #pragma unroll
    for (int nf = 0; nf < 4; nf++) {
        int col = bn + wn * 32 + nf * 8 + 2 * tg;
        float2 bv = *(const float2*)(bias + col);
        #pragma unroll
        for (int mf = 0; mf < 2; mf++) {
            int row = bm + wm * 32 + mf * 16 + g;
            float2 v0 = make_float2(acc[mf][nf][0] + bv.x, acc[mf][nf][1] + bv.y);
            float2 v1 = make_float2(acc[mf][nf][2] + bv.x, acc[mf][nf][3] + bv.y);
            if (res) {
                float2 r0 = *(const float2*)(res + (size_t)row * 512 + col);
                float2 r1 = *(const float2*)(res + (size_t)(row + 8) * 512 + col);
                v0.x += r0.x; v0.y += r0.y; v1.x += r1.x; v1.y += r1.y;
            }
            *(float2*)(C + (size_t)row * 512 + col) = v0;
            *(float2*)(C + (size_t)(row + 8) * 512 + col) = v1;
        }
    }
}

struct GemmSet {
    const float* W[3];
    const float* b[3];
    const float* r[3];
    float*       C[3];
};

template<bool TRANSW>
__global__ void __launch_bounds__(128, 5) gemm_tc_kernel(const float* __restrict__ A, GemmSet s) {
    int z = blockIdx.z;
    gemm_tc_core<TRANSW>(A, s.W[z], s.b[z], s.r[z], s.C[z]);
}

// ---------------- attention core: one block per (b, h), 256 threads ---------
template<int S>
__global__ void __launch_bounds__(256) attn_kernel(
    const float* __restrict__ Q, const float* __restrict__ Kp,
    const float* __restrict__ Vp, float* __restrict__ O)
{
    __shared__ float qs[25 * 64];
    __shared__ __align__(16) float kv[96 * 64];
    __shared__ float sc[25 * S];
    int b = blockIdx.x >> 3, h = blockIdx.x & 7;
    int tid = threadIdx.x;
    const float scale = 0.125f;
    size_t qbase = (size_t)b * 25 * 512 + h * 64;
    size_t kbase = (size_t)b * S  * 512 + h * 64;

    for (int i = tid; i < 25 * 64; i += 256) qs[i] = Q[qbase + (size_t)(i >> 6) * 512 + (i & 63)];
    for (int i = tid; i < S  * 64; i += 256) kv[i] = Kp[kbase + (size_t)(i >> 6) * 512 + (i & 63)];
    __syncthreads();

    for (int i = tid; i < 25 * S; i += 256) {
        int l = i / S, s = i - l * S;
        float acc = 0.f;
        #pragma unroll
        for (int e4 = 0; e4 < 16; e4++) {
            float4 q4 = *(const float4*)&qs[l * 64 + e4 * 4];
            float4 k4 = *(const float4*)&kv[s * 64 + e4 * 4];
            acc += q4.x * k4.x + q4.y * k4.y + q4.z * k4.z + q4.w * k4.w;
        }
        sc[i] = acc * scale;
    }
    __syncthreads();

    int warp = tid >> 5, lane = tid & 31;
    for (int l = warp; l < 25; l += 8) {
        float mx = -1e30f;
        for (int s = lane; s < S; s += 32) mx = fmaxf(mx, sc[l * S + s]);
        #pragma unroll
        for (int o = 16; o; o >>= 1) mx = fmaxf(mx, __shfl_xor_sync(~0u, mx, o));
        float sum = 0.f;
        for (int s = lane; s < S; s += 32) {
            float e = __expf(sc[l * S + s] - mx);
            sc[l * S + s] = e; sum += e;
        }
        #pragma unroll
        for (int o = 16; o; o >>= 1) sum += __shfl_xor_sync(~0u, sum, o);
        float inv = __fdividef(1.f, sum);
        for (int s = lane; s < S; s += 32) sc[l * S + s] *= inv;
    }
    __syncthreads();

    for (int i = tid; i < S * 64; i += 256) kv[i] = Vp[kbase + (size_t)(i >> 6) * 512 + (i & 63)];
    __syncthreads();

    for (int i = tid; i < 25 * 16; i += 256) {
        int l = i >> 4, e4 = (i & 15) * 4;
        float4 acc = make_float4(0.f, 0.f, 0.f, 0.f);
        const float* scl = &sc[l * S];
        #pragma unroll 4
        for (int s = 0; s < S; s++) {
            float w = scl[s];
            float4 v4 = *(const float4*)&kv[s * 64 + e4];
            acc.x += w * v4.x; acc.y += w * v4.y;
            acc.z += w * v4.z; acc.w += w * v4.w;
        }
        *(float4*)(&O[qbase + (size_t)l * 512 + e4]) = acc;
    }
}

// ---------------- LayerNorm over rows of 512 (warp per row) ------------------
__global__ void __launch_bounds__(256) ln_kernel(
    const float* __restrict__ in, const float* __restrict__ g,
    const float* __restrict__ bb, float* __restrict__ out, int M)
{
    int row = blockIdx.x * 8 + (threadIdx.x >> 5);
    int lane = threadIdx.x & 31;
    if (row >= M) return;
    const float* p = in + (size_t)row * 512;
    float v[16];
    float s = 0.f, s2 = 0.f;
    #pragma unroll
    for (int i = 0; i < 16; i++) {
        v[i] = p[lane + 32 * i];
        s += v[i]; s2 += v[i] * v[i];
    }
    #pragma unroll
    for (int o = 16; o; o >>= 1) {
        s  += __shfl_xor_sync(~0u, s,  o);
        s2 += __shfl_xor_sync(~0u, s2, o);
    }
    float mean = s * (1.f / 512.f);
    float var  = s2 * (1.f / 512.f) - mean * mean;
    float rstd = rsqrtf(var + 1e-5f);
    float* q = out + (size_t)row * 512;
    #pragma unroll
    for (int i = 0; i < 16; i++) {
        int d = lane + 32 * i;
        q[d] = (v[i] - mean) * rstd * g[d] + bb[d];
    }
}

// ---------------- tiled transposes -------------------------------------------
__global__ void transpose_in_kernel(const float* __restrict__ in, float* __restrict__ out) {
    __shared__ float tile[32][33];
    int tx = threadIdx.x, ty = threadIdx.y;
    int t0 = blockIdx.x * 32, b0 = blockIdx.y * 32, k = blockIdx.z;
    #pragma unroll
    for (int i = 0; i < 4; i++)
        tile[ty + 8 * i][tx] = in[(size_t)(b0 + ty + 8 * i) * 12800 + k * 512 + t0 + tx];
    __syncthreads();
    #pragma unroll
    for (int i = 0; i < 4; i++)
        out[(size_t)(t0 + ty + 8 * i) * 3200 + k * 128 + b0 + tx] = tile[tx][ty + 8 * i];
}
__global__ void transpose_out_kernel(const float* __restrict__ in, float* __restrict__ out) {
    __shared__ float tile[32][33];
    int tx = threadIdx.x, ty = threadIdx.y;
    int c0 = blockIdx.x * 32, b0 = blockIdx.y * 32, l = blockIdx.z;
    #pragma unroll
    for (int i = 0; i < 4; i++)
        tile[ty + 8 * i][tx] = in[(size_t)(c0 + ty + 8 * i) * 3200 + l * 128 + b0 + tx];
    __syncthreads();
    #pragma unroll
    for (int i = 0; i < 4; i++)
        out[(size_t)((b0 + ty + 8 * i) * 25 + l) * 512 + c0 + tx] = tile[tx][ty + 8 * i];
}

__global__ void zero_flags_kernel() {
    int i = blockIdx.x * 256 + threadIdx.x;
    if (i < 33 * 4 * 32) g_flags[i] = 0;
}

DEVF void spinwait(const int* p, int need) {
    int v;
    do {
        asm volatile("ld.acquire.gpu.global.b32 %0, [%1];" : "=r"(v) : "l"(p) : "memory");
    } while (v < need);
}

// ---------------- tensor-core LSTM wavefront, lag-2 + cp.async IO ------------
// 128 blocks = 32 layers x 4 chunks(32 batches). 160 threads: warps 0-3 compute,
// warp 4 = IO. B = [x(25); h(25); pad] raw fp32 bits (mma truncates to tf32),
// 4-slot rotation: step t reads slot t&3, h_t -> slot (t+1)&3, x_{t+2} prefetched
// by cp.async -> slot (t+2)&3 (wait_group 1 each step guarantees readiness).
// Flag value cached: acquire-poll only when cached < t+3.
#define BROWS 56
#define BSTR  40
__global__ void __launch_bounds__(160, 1) lstm_wave_kernel(
    const float* __restrict__ Wih, const float* __restrict__ Whh,
    const float* __restrict__ bih, const float* __restrict__ bhh)
{
    __shared__ __align__(16) unsigned Bsm[4][BROWS][BSTR];

    int layer = blockIdx.x & 31;
    int chunk = blockIdx.x >> 5;
    int b0 = chunk * 32;
    const float* in  = g_Y + (size_t)layer * YSTRIDE;
    float* outp      = g_Y + (size_t)(layer + 1) * YSTRIDE;
    const int* inflag = g_flags + (layer * 4 + chunk) * 32;
    int* outflag      = g_flags + ((layer + 1) * 4 + chunk) * 32;

    int tid = threadIdx.x;
    int warp = tid >> 5, lane = tid & 31;
    int g = lane >> 2, tg = lane & 3;

    for (int i = tid; i < 4 * BROWS * BSTR; i += 160) ((unsigned*)Bsm)[i] = 0;

    unsigned afr[2][7][4];
    float bias_i = 0.f, bias_f = 0.f, bias_g = 0.f, bias_o = 0.f;
    int u = warp * 8 + g;
    bool isComp = (warp < 4);
    bool valid = isComp && (u < 25);
    if (isComp) {
        const float* WI = Wih + (size_t)layer * 2500;
        const float* WH = Whh + (size_t)layer * 2500;
        #pragma unroll
        for (int T = 0; T < 2; T++) {
            int rowA = (T == 0 ? 0 : 50) + u;
            int rowB = (T == 0 ? 25 : 75) + u;
            #pragma unroll
            for (int ks = 0; ks < 7; ks++) {
                #pragma unroll
                for (int q = 0; q < 4; q++) {
                    int k = ks * 8 + tg + (q >= 2 ? 4 : 0);
                    int row = (q & 1) ? rowB : rowA;
                    float w = 0.f;
                    if (valid) {
                        if (k < 25)      w = WI[row * 25 + k];
                        else if (k < 50) w = WH[row * 25 + (k - 25)];
                    }
                    afr[T][ks][q] = totf(w);
                }
            }
        }
        if (valid) {
            bias_i = bih[layer * 100 + u]      + bhh[layer * 100 + u];
            bias_f = bih[layer * 100 + 25 + u] + bhh[layer * 100 + 25 + u];
            bias_g = bih[layer * 100 + 50 + u] + bhh[layer * 100 + 50 + u];
            bias_o = bih[layer * 100 + 75 + u] + bhh[layer * 100 + 75 + u];
        }
    }
    float c[8];
    #pragma unroll
    for (int i = 0; i < 8; i++) c[i] = 0.f;
    __syncthreads();

    unsigned bsmb = (unsigned)__cvta_generic_to_shared(&Bsm[0][0][0]);

    // prologue: x_0 -> slot0, x_1 -> slot1 (raw fp32 bits)
    if (warp == 4) {
        if (layer > 0 && lane == 0) spinwait(inflag, 2);
        __syncwarp();
        #pragma unroll
        for (int p = 0; p < 2; p++) {
            const float* src = in + (size_t)p * 3200 + b0;
            #pragma unroll
            for (int k = 0; k < 25; k++)
                Bsm[p][k][lane] = __float_as_uint(src[k * 128 + lane]);
        }
    }
    __syncthreads();

    int cached = 2;
    for (int t = 0; t < 512; t++) {
        int s = t & 3;
        if (isComp) {
            float acc0[4][4], acc1[4][4];
            #pragma unroll
            for (int nf = 0; nf < 4; nf++) {
                acc0[nf][0] = bias_i; acc0[nf][1] = bias_i;
                acc0[nf][2] = bias_f; acc0[nf][3] = bias_f;
                acc1[nf][0] = bias_g; acc1[nf][1] = bias_g;
                acc1[nf][2] = bias_o; acc1[nf][3] = bias_o;
            }
            const unsigned* Bp = &Bsm[s][0][0];
            #pragma unroll
            for (int ks = 0; ks < 7; ks++) {
                int r0 = (ks * 8 + tg) * BSTR;
                #pragma unroll
                for (int nf = 0; nf < 4; nf++) {
                    unsigned b0v = Bp[r0 + nf * 8 + g];
                    unsigned b1v = Bp[r0 + 4 * BSTR + nf * 8 + g];
                    mma_tf32(acc0[nf], afr[0][ks], b0v, b1v);
                    mma_tf32(acc1[nf], afr[1][ks], b0v, b1v);
                }
            }
            unsigned* Bn = &Bsm[(t + 1) & 3][0][0];
            #pragma unroll
            for (int nf = 0; nf < 4; nf++) {
                float i0 = sig_fast(acc0[nf][0]),  i1 = sig_fast(acc0[nf][1]);
                float f0 = sig_fast(acc0[nf][2]),  f1 = sig_fast(acc0[nf][3]);
                float q0 = tanh_fast(acc1[nf][0]), q1 = tanh_fast(acc1[nf][1]);
                float o0 = sig_fast(acc1[nf][2]),  o1 = sig_fast(acc1[nf][3]);
                c[2 * nf]     = f0 * c[2 * nf]     + i0 * q0;
                c[2 * nf + 1] = f1 * c[2 * nf + 1] + i1 * q1;
                float h0 = o0 * tanh_fast(c[2 * nf]);
                float h1 = o1 * tanh_fast(c[2 * nf + 1]);
                if (valid) {
                    uint2 hp = make_uint2(__float_as_uint(h0), __float_as_uint(h1));
                    *(uint2*)&Bn[(25 + u) * BSTR + nf * 8 + 2 * tg] = hp;
                    *(float2*)(outp + (size_t)t * 3200 + u * 128 + b0 + nf * 8 + 2 * tg)
                        = make_float2(h0, h1);
                }
            }
        } else {
            if (t < 510) {
                if (layer > 0 && lane == 0) {
                    int need = t + 3;
                    if (cached < need) {
                        int v;
                        do {
                            asm volatile("ld.acquire.gpu.global.b32 %0, [%1];" : "=r"(v) : "l"(inflag) : "memory");
                        } while (v < need);
                        cached = v;
                    }
                }
                __syncwarp();
                const float* src = in + (size_t)(t + 2) * 3200 + b0 + lane;
                unsigned dst = bsmb + ((((t + 2) & 3) * BROWS) * BSTR + lane) * 4;
                #pragma unroll
                for (int k = 0; k < 25; k++)
                    cpasync4(dst + k * BSTR * 4, src + k * 128);
                cp_commit();
                cp_wait1();
            } else {
                cp_wait0();
            }
        }
        __syncthreads();
        if (tid == 0) {
            int nv = t + 1;
            asm volatile("st.release.gpu.global.b32 [%0], %1;" :: "l"(outflag), "r"(nv) : "memory");
        }
    }
}

// ---------------- launcher ---------------------------------------------------
extern "C" void kernel_launch(void* const* d_in, const int* in_sizes, int n_in,
                              void* d_out, int out_size)
{
    const float* x     = (const float*)d_in[0];
    const float* cross = (const float*)d_in[1];
    const float* Wq_s = (const float*)d_in[2];  const float* bq_s = (const float*)d_in[3];
    const float* Wk_s = (const float*)d_in[4];  const float* bk_s = (const float*)d_in[5];
    const float* Wv_s = (const float*)d_in[6];  const float* bv_s = (const float*)d_in[7];
    const float* Wo_s = (const float*)d_in[8];  const float* bo_s = (const float*)d_in[9];
    const float* Wq_c = (const float*)d_in[10]; const float* bq_c = (const float*)d_in[11];
    const float* Wk_c = (const float*)d_in[12]; const float* bk_c = (const float*)d_in[13];
    const float* Wv_c = (const float*)d_in[14]; const float* bv_c = (const float*)d_in[15];
    const float* Wo_c = (const float*)d_in[16]; const float* bo_c = (const float*)d_in[17];
    const float* g1 = (const float*)d_in[18]; const float* b1 = (const float*)d_in[19];
    const float* g2 = (const float*)d_in[20]; const float* b2 = (const float*)d_in[21];
    const float* g3 = (const float*)d_in[22]; const float* b3 = (const float*)d_in[23];
    const float* W_ih = (const float*)d_in[24];
    const float* W_hh = (const float*)d_in[25];
    const float* b_ih = (const float*)d_in[26];
    const float* b_hh = (const float*)d_in[27];
    const float* Wc = (const float*)d_in[28]; const float* bc = (const float*)d_in[29];
    float* out = (float*)d_out;

    float *gq, *gk, *gv, *gctx, *gx1, *gx2, *gtmp, *gyt, *gY;
    cudaGetSymbolAddress((void**)&gq,   g_q);
    cudaGetSymbolAddress((void**)&gk,   g_k);
    cudaGetSymbolAddress((void**)&gv,   g_v);
    cudaGetSymbolAddress((void**)&gctx, g_ctx);
    cudaGetSymbolAddress((void**)&gx1,  g_x1);
    cudaGetSymbolAddress((void**)&gx2,  g_x2);
    cudaGetSymbolAddress((void**)&gtmp, g_tmp);
    cudaGetSymbolAddress((void**)&gyt,  g_yt);
    cudaGetSymbolAddress((void**)&gY,   g_Y);

    const int M1 = 3200;    // B*L
    zero_flags_kernel<<<17, 256>>>();

    // ---- self attention ----
    {
        GemmSet s = {{Wq_s, Wk_s, Wv_s}, {bq_s, bk_s, bv_s},
                     {nullptr, nullptr, nullptr}, {gq, gk, gv}};
        gemm_tc_kernel<false><<<dim3(50, 8, 3), 128>>>(x, s);
    }
    attn_kernel<25><<<128 * 8, 256>>>(gq, gk, gv, gctx);
    {
        GemmSet s = {{Wo_s, nullptr, nullptr}, {bo_s, nullptr, nullptr},
                     {x, nullptr, nullptr}, {gtmp, nullptr, nullptr}};
        gemm_tc_kernel<false><<<dim3(50, 8, 1), 128>>>(gctx, s);
    }
    ln_kernel<<<M1 / 8, 256>>>(gtmp, g1, b1, gx1, M1);

    // ---- cross attention ----
    {
        GemmSet s = {{Wq_c, nullptr, nullptr}, {bq_c, nullptr, nullptr},
                     {nullptr, nullptr, nullptr}, {gq, nullptr, nullptr}};
        gemm_tc_kernel<false><<<dim3(50, 8, 1), 128>>>(gx1, s);
    }
    {
        GemmSet s = {{Wk_c, Wv_c, nullptr}, {bk_c, bv_c, nullptr},
                     {nullptr, nullptr, nullptr}, {gk, gv, nullptr}};
        gemm_tc_kernel<false><<<dim3(192, 8, 2), 128>>>(cross, s);
    }
    attn_kernel<96><<<128 * 8, 256>>>(gq, gk, gv, gctx);
    {
        GemmSet s = {{Wo_c, nullptr, nullptr}, {bo_c, nullptr, nullptr},
                     {gx1, nullptr, nullptr}, {gtmp, nullptr, nullptr}};
        gemm_tc_kernel<false><<<dim3(50, 8, 1), 128>>>(gctx, s);
    }
    ln_kernel<<<M1 / 8, 256>>>(gtmp, g2, b2, gx2, M1);

    // ---- LSTM wavefront over feature axis ----
    transpose_in_kernel<<<dim3(16, 4, 25), dim3(32, 8)>>>(gx2, gY);
    lstm_wave_kernel<<<128, 160>>>(W_ih, W_hh, b_ih, b_hh);

    // ---- pointwise conv + residual + final LN ----
    transpose_out_kernel<<<dim3(16, 4, 25), dim3(32, 8)>>>(gY + 32ull * YSTRIDE, gyt);
    {
        GemmSet s = {{Wc, nullptr, nullptr}, {bc, nullptr, nullptr},
                     {gx2, nullptr, nullptr}, {gtmp, nullptr, nullptr}};
        gemm_tc_kernel<true><<<dim3(50, 8, 1), 128>>>(gyt, s);
    }
    ln_kernel<<<M1 / 8, 256>>>(gtmp, g3, b3, out, M1);
}

// round 13
// speedup vs baseline: 1.1543x; 1.0822x over previous
#include <cuda_runtime.h>
#include <cstddef>

#define DEVF __device__ __forceinline__
typedef unsigned long long ull;

// ---------------- scratch (device globals; no allocations allowed) ----------
__device__ float g_q  [3200 * 512];
__device__ float g_k  [12288 * 512];
__device__ float g_v  [12288 * 512];
__device__ float g_ctx[3200 * 512];
__device__ float g_x1 [3200 * 512];
__device__ float g_x2 [3200 * 512];
__device__ float g_tmp[3200 * 512];
__device__ float g_yt [3200 * 512];

// LSTM wavefront buffers: Y[l][t][k][b], l = 0..32, t<512, k<25, b<128
#define YSTRIDE 1638400   // 512*25*128
__device__ float g_Y[33ull * YSTRIDE];
__device__ int   g_flags[33 * 4 * 32];   // (layer,chunk) progress, 128B padded

// ---------------- activations ------------------------------------------------
DEVF float tanh_fast(float x) {
    float y; asm("tanh.approx.f32 %0, %1;" : "=f"(y) : "f"(x)); return y;
}
DEVF float sig_fast(float x) { return fmaf(tanh_fast(0.5f * x), 0.5f, 0.5f); }

// ---------------- tf32 helpers -----------------------------------------------
DEVF unsigned totf(float x) {
    unsigned r; asm("cvt.rna.tf32.f32 %0, %1;" : "=r"(r) : "f"(x)); return r;
}
DEVF void mma_tf32(float* c, const unsigned* a, unsigned b0, unsigned b1) {
    asm("mma.sync.aligned.m16n8k8.row.col.f32.tf32.tf32.f32 "
        "{%0,%1,%2,%3}, {%4,%5,%6,%7}, {%8,%9}, {%0,%1,%2,%3};"
        : "+f"(c[0]), "+f"(c[1]), "+f"(c[2]), "+f"(c[3])
        : "r"(a[0]), "r"(a[1]), "r"(a[2]), "r"(a[3]), "r"(b0), "r"(b1));
}

DEVF void cpasync16(unsigned dst, const void* src) {
    asm volatile("cp.async.cg.shared.global [%0], [%1], 16;" :: "r"(dst), "l"(src));
}
DEVF void cpasync4(unsigned dst, const void* src) {
    asm volatile("cp.async.ca.shared.global [%0], [%1], 4;" :: "r"(dst), "l"(src));
}
DEVF void cp_commit() { asm volatile("cp.async.commit_group;"); }
DEVF void cp_wait2()  { asm volatile("cp.async.wait_group 2;"); }
DEVF void cp_wait1()  { asm volatile("cp.async.wait_group 1;"); }
DEVF void cp_wait0()  { asm volatile("cp.async.wait_group 0;"); }

// ---------------- tf32 tensor-core GEMM, cp.async 4-stage, BK=16 -------------
// C[.,512] = A[.,512] @ W (+bias)(+res). TRANSW: W stored [N,K] else [K,N].
// ONE barrier per k-iteration (top barrier covers WAR on the cp target slot).
#define ASTR 20
#define AWRD (64 * ASTR)       // 1280
#define BWRD 1296              // >= max(16*72, 64*20)
template<bool TRANSW>
DEVF void gemm_tc_core(const float* __restrict__ A, const float* __restrict__ W,
                       const float* __restrict__ bias, const float* __restrict__ res,
                       float* __restrict__ C)
{
    __shared__ __align__(16) float As[4][AWRD];
    __shared__ __align__(16) float Bsm[4][BWRD];

    int tid = threadIdx.x;
    int bm = blockIdx.x * 64, bn = blockIdx.y * 64;
    int lane = tid & 31, wid = tid >> 5;
    int wm = wid & 1, wn = wid >> 1;
    int g = lane >> 2, tg = lane & 3;

    float acc[2][4][4];
    #pragma unroll
    for (int i = 0; i < 2; i++)
        #pragma unroll
        for (int j = 0; j < 4; j++)
            #pragma unroll
            for (int q = 0; q < 4; q++) acc[i][j][q] = 0.f;

    int ar = tid >> 1, ac = (tid & 1) * 8;
    const float* Asrc = A + (size_t)(bm + ar) * 512 + ac;
    int kk = tid >> 3, nn = (tid & 7) * 8;
    int nr = tid >> 1, kc = (tid & 1) * 8;
    const float* Bsrc = TRANSW ? (W + (size_t)(bn + nr) * 512 + kc)
                               : (W + (size_t)kk * 512 + bn + nn);

    unsigned asb = (unsigned)__cvta_generic_to_shared(&As[0][0]);
    unsigned bsb = (unsigned)__cvta_generic_to_shared(&Bsm[0][0]);
    unsigned adst = asb + (ar * ASTR + ac) * 4;
    unsigned bdst = bsb + (TRANSW ? (nr * ASTR + kc) : (kk * 72 + nn)) * 4;

    #pragma unroll
    for (int p = 0; p < 3; p++) {
        int k0 = p * 16;
        cpasync16(adst + p * AWRD * 4, Asrc + k0);
        cpasync16(adst + p * AWRD * 4 + 16, Asrc + k0 + 4);
        const float* bs = TRANSW ? (Bsrc + k0) : (Bsrc + (size_t)k0 * 512);
        cpasync16(bdst + p * BWRD * 4, bs);
        cpasync16(bdst + p * BWRD * 4 + 16, bs + 4);
        cp_commit();
    }

    int am0 = wm * 32 + g;

    for (int it = 0; it < 32; it++) {
        int st = it & 3;
        cp_wait2();
        __syncthreads();
        if (it + 3 < 32) {
            int tl = it + 3, ns = tl & 3;
            int k0 = tl * 16;
            cpasync16(adst + ns * AWRD * 4, Asrc + k0);
            cpasync16(adst + ns * AWRD * 4 + 16, Asrc + k0 + 4);
            const float* bs = TRANSW ? (Bsrc + k0) : (Bsrc + (size_t)k0 * 512);
            cpasync16(bdst + ns * BWRD * 4, bs);
            cpasync16(bdst + ns * BWRD * 4 + 16, bs + 4);
        }
        cp_commit();

        const unsigned* Au = (const unsigned*)As[st];
        const unsigned* Bu = (const unsigned*)Bsm[st];
        #pragma unroll
        for (int ks = 0; ks < 2; ks++) {
            int klo = ks * 8 + tg;
            unsigned afr[2][4];
            #pragma unroll
            for (int mf = 0; mf < 2; mf++) {
                int m = am0 + mf * 16;
                afr[mf][0] = Au[m * ASTR + klo];
                afr[mf][1] = Au[(m + 8) * ASTR + klo];
                afr[mf][2] = Au[m * ASTR + klo + 4];
                afr[mf][3] = Au[(m + 8) * ASTR + klo + 4];
            }
            #pragma unroll
            for (int nf = 0; nf < 4; nf++) {
                int col = wn * 32 + nf * 8 + g;
                unsigned b0, b1;
                if (!TRANSW) {
                    b0 = Bu[klo * 72 + col];
                    b1 = Bu[(klo + 4) * 72 + col];
                } else {
                    b0 = Bu[col * ASTR + klo];
                    b1 = Bu[col * ASTR + klo + 4];
                }
                mma_tf32(acc[0][nf], afr[0], b0, b1);
                mma_tf32(acc[1][nf], afr[1], b0, b1);
            }
        }
    }

    #pragma unroll
    for (int nf = 0; nf < 4; nf++) {
        int col = bn + wn * 32 + nf * 8 + 2 * tg;
        float2 bv = *(const float2*)(bias + col);
        #pragma unroll
        for (int mf = 0; mf < 2; mf++) {
            int row = bm + wm * 32 + mf * 16 + g;
            float2 v0 = make_float2(acc[mf][nf][0] + bv.x, acc[mf][nf][1] + bv.y);
            float2 v1 = make_float2(acc[mf][nf][2] + bv.x, acc[mf][nf][3] + bv.y);
            if (res) {
                float2 r0 = *(const float2*)(res + (size_t)row * 512 + col);
                float2 r1 = *(const float2*)(res + (size_t)(row + 8) * 512 + col);
                v0.x += r0.x; v0.y += r0.y; v1.x += r1.x; v1.y += r1.y;
            }
            *(float2*)(C + (size_t)row * 512 + col) = v0;
            *(float2*)(C + (size_t)(row + 8) * 512 + col) = v1;
        }
    }
}

struct GemmSet {
    const float* W[3];
    const float* b[3];
    const float* r[3];
    float*       C[3];
};

template<bool TRANSW>
__global__ void __launch_bounds__(128, 5) gemm_tc_kernel(const float* __restrict__ A, GemmSet s) {
    int z = blockIdx.z;
    gemm_tc_core<TRANSW>(A, s.W[z], s.b[z], s.r[z], s.C[z]);
}

// ---------------- attention core: one block per (b, h), 256 threads ---------
template<int S>
__global__ void __launch_bounds__(256) attn_kernel(
    const float* __restrict__ Q, const float* __restrict__ Kp,
    const float* __restrict__ Vp, float* __restrict__ O)
{
    __shared__ float qs[25 * 64];
    __shared__ __align__(16) float kv[96 * 64];
    __shared__ float sc[25 * S];
    int b = blockIdx.x >> 3, h = blockIdx.x & 7;
    int tid = threadIdx.x;
    const float scale = 0.125f;
    size_t qbase = (size_t)b * 25 * 512 + h * 64;
    size_t kbase = (size_t)b * S  * 512 + h * 64;

    for (int i = tid; i < 25 * 64; i += 256) qs[i] = Q[qbase + (size_t)(i >> 6) * 512 + (i & 63)];
    for (int i = tid; i < S  * 64; i += 256) kv[i] = Kp[kbase + (size_t)(i >> 6) * 512 + (i & 63)];
    __syncthreads();

    for (int i = tid; i < 25 * S; i += 256) {
        int l = i / S, s = i - l * S;
        float acc = 0.f;
        #pragma unroll
        for (int e4 = 0; e4 < 16; e4++) {
            float4 q4 = *(const float4*)&qs[l * 64 + e4 * 4];
            float4 k4 = *(const float4*)&kv[s * 64 + e4 * 4];
            acc += q4.x * k4.x + q4.y * k4.y + q4.z * k4.z + q4.w * k4.w;
        }
        sc[i] = acc * scale;
    }
    __syncthreads();

    int warp = tid >> 5, lane = tid & 31;
    for (int l = warp; l < 25; l += 8) {
        float mx = -1e30f;
        for (int s = lane; s < S; s += 32) mx = fmaxf(mx, sc[l * S + s]);
        #pragma unroll
        for (int o = 16; o; o >>= 1) mx = fmaxf(mx, __shfl_xor_sync(~0u, mx, o));
        float sum = 0.f;
        for (int s = lane; s < S; s += 32) {
            float e = __expf(sc[l * S + s] - mx);
            sc[l * S + s] = e; sum += e;
        }
        #pragma unroll
        for (int o = 16; o; o >>= 1) sum += __shfl_xor_sync(~0u, sum, o);
        float inv = __fdividef(1.f, sum);
        for (int s = lane; s < S; s += 32) sc[l * S + s] *= inv;
    }
    __syncthreads();

    for (int i = tid; i < S * 64; i += 256) kv[i] = Vp[kbase + (size_t)(i >> 6) * 512 + (i & 63)];
    __syncthreads();

    for (int i = tid; i < 25 * 16; i += 256) {
        int l = i >> 4, e4 = (i & 15) * 4;
        float4 acc = make_float4(0.f, 0.f, 0.f, 0.f);
        const float* scl = &sc[l * S];
        #pragma unroll 4
        for (int s = 0; s < S; s++) {
            float w = scl[s];
            float4 v4 = *(const float4*)&kv[s * 64 + e4];
            acc.x += w * v4.x; acc.y += w * v4.y;
            acc.z += w * v4.z; acc.w += w * v4.w;
        }
        *(float4*)(&O[qbase + (size_t)l * 512 + e4]) = acc;
    }
}

// ---------------- LayerNorm over rows of 512 (warp per row) ------------------
__global__ void __launch_bounds__(256) ln_kernel(
    const float* __restrict__ in, const float* __restrict__ g,
    const float* __restrict__ bb, float* __restrict__ out, int M)
{
    int row = blockIdx.x * 8 + (threadIdx.x >> 5);
    int lane = threadIdx.x & 31;
    if (row >= M) return;
    const float* p = in + (size_t)row * 512;
    float v[16];
    float s = 0.f, s2 = 0.f;
    #pragma unroll
    for (int i = 0; i < 16; i++) {
        v[i] = p[lane + 32 * i];
        s += v[i]; s2 += v[i] * v[i];
    }
    #pragma unroll
    for (int o = 16; o; o >>= 1) {
        s  += __shfl_xor_sync(~0u, s,  o);
        s2 += __shfl_xor_sync(~0u, s2, o);
    }
    float mean = s * (1.f / 512.f);
    float var  = s2 * (1.f / 512.f) - mean * mean;
    float rstd = rsqrtf(var + 1e-5f);
    float* q = out + (size_t)row * 512;
    #pragma unroll
    for (int i = 0; i < 16; i++) {
        int d = lane + 32 * i;
        q[d] = (v[i] - mean) * rstd * g[d] + bb[d];
    }
}

// ---------------- tiled transposes -------------------------------------------
__global__ void transpose_in_kernel(const float* __restrict__ in, float* __restrict__ out) {
    __shared__ float tile[32][33];
    int tx = threadIdx.x, ty = threadIdx.y;
    int t0 = blockIdx.x * 32, b0 = blockIdx.y * 32, k = blockIdx.z;
    #pragma unroll
    for (int i = 0; i < 4; i++)
        tile[ty + 8 * i][tx] = in[(size_t)(b0 + ty + 8 * i) * 12800 + k * 512 + t0 + tx];
    __syncthreads();
    #pragma unroll
    for (int i = 0; i < 4; i++)
        out[(size_t)(t0 + ty + 8 * i) * 3200 + k * 128 + b0 + tx] = tile[tx][ty + 8 * i];
}
__global__ void transpose_out_kernel(const float* __restrict__ in, float* __restrict__ out) {
    __shared__ float tile[32][33];
    int tx = threadIdx.x, ty = threadIdx.y;
    int c0 = blockIdx.x * 32, b0 = blockIdx.y * 32, l = blockIdx.z;
    #pragma unroll
    for (int i = 0; i < 4; i++)
        tile[ty + 8 * i][tx] = in[(size_t)(c0 + ty + 8 * i) * 3200 + l * 128 + b0 + tx];
    __syncthreads();
    #pragma unroll
    for (int i = 0; i < 4; i++)
        out[(size_t)((b0 + ty + 8 * i) * 25 + l) * 512 + c0 + tx] = tile[tx][ty + 8 * i];
}

__global__ void zero_flags_kernel() {
    int i = blockIdx.x * 256 + threadIdx.x;
    if (i < 33 * 4 * 32) g_flags[i] = 0;
}

DEVF void spinwait(const int* p, int need) {
    int v;
    do {
        asm volatile("ld.acquire.gpu.global.b32 %0, [%1];" : "=r"(v) : "l"(p) : "memory");
    } while (v < need);
}

// ---------------- tensor-core LSTM wavefront, 8 compute warps ----------------
// 128 blocks = 32 layers x 4 chunks(32 batches). 288 threads = 9 warps:
// warps 0-7 compute (warp w: unit group w&3, batch half w>>2 -> 2 nf each),
// warp 8 = IO (cached flag + cp.async x prefetch). 4-slot rotation, lag 2:
// step t reads slot t&3, h_t -> slot (t+1)&3, x_{t+2} -> slot (t+2)&3.
#define BROWS 56
#define BSTR  40
__global__ void __launch_bounds__(288, 1) lstm_wave_kernel(
    const float* __restrict__ Wih, const float* __restrict__ Whh,
    const float* __restrict__ bih, const float* __restrict__ bhh)
{
    __shared__ __align__(16) unsigned Bsm[4][BROWS][BSTR];

    int layer = blockIdx.x & 31;
    int chunk = blockIdx.x >> 5;
    int b0 = chunk * 32;
    const float* in  = g_Y + (size_t)layer * YSTRIDE;
    float* outp      = g_Y + (size_t)(layer + 1) * YSTRIDE;
    const int* inflag = g_flags + (layer * 4 + chunk) * 32;
    int* outflag      = g_flags + ((layer + 1) * 4 + chunk) * 32;

    int tid = threadIdx.x;
    int warp = tid >> 5, lane = tid & 31;
    int g = lane >> 2, tg = lane & 3;

    for (int i = tid; i < 4 * BROWS * BSTR; i += 288) ((unsigned*)Bsm)[i] = 0;

    bool isComp = (warp < 8);
    int pair = warp & 3;          // unit group
    int half = warp >> 2;         // batch half (nf base = half*2)
    int u = pair * 8 + g;
    bool valid = isComp && (u < 25);

    unsigned afr[2][7][4];
    float bias_i = 0.f, bias_f = 0.f, bias_g = 0.f, bias_o = 0.f;
    if (isComp) {
        const float* WI = Wih + (size_t)layer * 2500;
        const float* WH = Whh + (size_t)layer * 2500;
        #pragma unroll
        for (int T = 0; T < 2; T++) {
            int rowA = (T == 0 ? 0 : 50) + u;
            int rowB = (T == 0 ? 25 : 75) + u;
            #pragma unroll
            for (int ks = 0; ks < 7; ks++) {
                #pragma unroll
                for (int q = 0; q < 4; q++) {
                    int k = ks * 8 + tg + (q >= 2 ? 4 : 0);
                    int row = (q & 1) ? rowB : rowA;
                    float w = 0.f;
                    if (valid) {
                        if (k < 25)      w = WI[row * 25 + k];
                        else if (k < 50) w = WH[row * 25 + (k - 25)];
                    }
                    afr[T][ks][q] = totf(w);
                }
            }
        }
        if (valid) {
            bias_i = bih[layer * 100 + u]      + bhh[layer * 100 + u];
            bias_f = bih[layer * 100 + 25 + u] + bhh[layer * 100 + 25 + u];
            bias_g = bih[layer * 100 + 50 + u] + bhh[layer * 100 + 50 + u];
            bias_o = bih[layer * 100 + 75 + u] + bhh[layer * 100 + 75 + u];
        }
    }
    float c[4];
    #pragma unroll
    for (int i = 0; i < 4; i++) c[i] = 0.f;
    __syncthreads();

    unsigned bsmb = (unsigned)__cvta_generic_to_shared(&Bsm[0][0][0]);

    // prologue: x_0 -> slot0, x_1 -> slot1 (raw fp32 bits)
    if (warp == 8) {
        if (layer > 0 && lane == 0) spinwait(inflag, 2);
        __syncwarp();
        #pragma unroll
        for (int p = 0; p < 2; p++) {
            const float* src = in + (size_t)p * 3200 + b0;
            #pragma unroll
            for (int k = 0; k < 25; k++)
                Bsm[p][k][lane] = __float_as_uint(src[k * 128 + lane]);
        }
    }
    __syncthreads();

    int cached = 2;
    for (int t = 0; t < 512; t++) {
        int s = t & 3;
        if (isComp) {
            float acc0[2][4], acc1[2][4];
            #pragma unroll
            for (int j = 0; j < 2; j++) {
                acc0[j][0] = bias_i; acc0[j][1] = bias_i;
                acc0[j][2] = bias_f; acc0[j][3] = bias_f;
                acc1[j][0] = bias_g; acc1[j][1] = bias_g;
                acc1[j][2] = bias_o; acc1[j][3] = bias_o;
            }
            const unsigned* Bp = &Bsm[s][0][0];
            #pragma unroll
            for (int ks = 0; ks < 7; ks++) {
                int r0 = (ks * 8 + tg) * BSTR;
                #pragma unroll
                for (int j = 0; j < 2; j++) {
                    int nf = half * 2 + j;
                    unsigned b0v = Bp[r0 + nf * 8 + g];
                    unsigned b1v = Bp[r0 + 4 * BSTR + nf * 8 + g];
                    mma_tf32(acc0[j], afr[0][ks], b0v, b1v);
                    mma_tf32(acc1[j], afr[1][ks], b0v, b1v);
                }
            }
            unsigned* Bn = &Bsm[(t + 1) & 3][0][0];
            #pragma unroll
            for (int j = 0; j < 2; j++) {
                int nf = half * 2 + j;
                float i0 = sig_fast(acc0[j][0]),  i1 = sig_fast(acc0[j][1]);
                float f0 = sig_fast(acc0[j][2]),  f1 = sig_fast(acc0[j][3]);
                float q0 = tanh_fast(acc1[j][0]), q1 = tanh_fast(acc1[j][1]);
                float o0 = sig_fast(acc1[j][2]),  o1 = sig_fast(acc1[j][3]);
                c[2 * j]     = f0 * c[2 * j]     + i0 * q0;
                c[2 * j + 1] = f1 * c[2 * j + 1] + i1 * q1;
                float h0 = o0 * tanh_fast(c[2 * j]);
                float h1 = o1 * tanh_fast(c[2 * j + 1]);
                if (valid) {
                    uint2 hp = make_uint2(__float_as_uint(h0), __float_as_uint(h1));
                    *(uint2*)&Bn[(25 + u) * BSTR + nf * 8 + 2 * tg] = hp;
                    *(float2*)(outp + (size_t)t * 3200 + u * 128 + b0 + nf * 8 + 2 * tg)
                        = make_float2(h0, h1);
                }
            }
        } else {
            if (t < 510) {
                if (layer > 0 && lane == 0) {
                    int need = t + 3;
                    if (cached < need) {
                        int v;
                        do {
                            asm volatile("ld.acquire.gpu.global.b32 %0, [%1];" : "=r"(v) : "l"(inflag) : "memory");
                        } while (v < need);
                        cached = v;
                    }
                }
                __syncwarp();
                const float* src = in + (size_t)(t + 2) * 3200 + b0 + lane;
                unsigned dst = bsmb + ((((t + 2) & 3) * BROWS) * BSTR + lane) * 4;
                #pragma unroll
                for (int k = 0; k < 25; k++)
                    cpasync4(dst + k * BSTR * 4, src + k * 128);
                cp_commit();
                cp_wait1();
            } else {
                cp_wait0();
            }
        }
        __syncthreads();
        if (tid == 0) {
            int nv = t + 1;
            asm volatile("st.release.gpu.global.b32 [%0], %1;" :: "l"(outflag), "r"(nv) : "memory");
        }
    }
}

// ---------------- launcher ---------------------------------------------------
extern "C" void kernel_launch(void* const* d_in, const int* in_sizes, int n_in,
                              void* d_out, int out_size)
{
    const float* x     = (const float*)d_in[0];
    const float* cross = (const float*)d_in[1];
    const float* Wq_s = (const float*)d_in[2];  const float* bq_s = (const float*)d_in[3];
    const float* Wk_s = (const float*)d_in[4];  const float* bk_s = (const float*)d_in[5];
    const float* Wv_s = (const float*)d_in[6];  const float* bv_s = (const float*)d_in[7];
    const float* Wo_s = (const float*)d_in[8];  const float* bo_s = (const float*)d_in[9];
    const float* Wq_c = (const float*)d_in[10]; const float* bq_c = (const float*)d_in[11];
    const float* Wk_c = (const float*)d_in[12]; const float* bk_c = (const float*)d_in[13];
    const float* Wv_c = (const float*)d_in[14]; const float* bv_c = (const float*)d_in[15];
    const float* Wo_c = (const float*)d_in[16]; const float* bo_c = (const float*)d_in[17];
    const float* g1 = (const float*)d_in[18]; const float* b1 = (const float*)d_in[19];
    const float* g2 = (const float*)d_in[20]; const float* b2 = (const float*)d_in[21];
    const float* g3 = (const float*)d_in[22]; const float* b3 = (const float*)d_in[23];
    const float* W_ih = (const float*)d_in[24];
    const float* W_hh = (const float*)d_in[25];
    const float* b_ih = (const float*)d_in[26];
    const float* b_hh = (const float*)d_in[27];
    const float* Wc = (const float*)d_in[28]; const float* bc = (const float*)d_in[29];
    float* out = (float*)d_out;

    float *gq, *gk, *gv, *gctx, *gx1, *gx2, *gtmp, *gyt, *gY;
    cudaGetSymbolAddress((void**)&gq,   g_q);
    cudaGetSymbolAddress((void**)&gk,   g_k);
    cudaGetSymbolAddress((void**)&gv,   g_v);
    cudaGetSymbolAddress((void**)&gctx, g_ctx);
    cudaGetSymbolAddress((void**)&gx1,  g_x1);
    cudaGetSymbolAddress((void**)&gx2,  g_x2);
    cudaGetSymbolAddress((void**)&gtmp, g_tmp);
    cudaGetSymbolAddress((void**)&gyt,  g_yt);
    cudaGetSymbolAddress((void**)&gY,   g_Y);

    const int M1 = 3200;    // B*L
    zero_flags_kernel<<<17, 256>>>();

    // ---- self attention ----
    {
        GemmSet s = {{Wq_s, Wk_s, Wv_s}, {bq_s, bk_s, bv_s},
                     {nullptr, nullptr, nullptr}, {gq, gk, gv}};
        gemm_tc_kernel<false><<<dim3(50, 8, 3), 128>>>(x, s);
    }
    attn_kernel<25><<<128 * 8, 256>>>(gq, gk, gv, gctx);
    {
        GemmSet s = {{Wo_s, nullptr, nullptr}, {bo_s, nullptr, nullptr},
                     {x, nullptr, nullptr}, {gtmp, nullptr, nullptr}};
        gemm_tc_kernel<false><<<dim3(50, 8, 1), 128>>>(gctx, s);
    }
    ln_kernel<<<M1 / 8, 256>>>(gtmp, g1, b1, gx1, M1);

    // ---- cross attention ----
    {
        GemmSet s = {{Wq_c, nullptr, nullptr}, {bq_c, nullptr, nullptr},
                     {nullptr, nullptr, nullptr}, {gq, nullptr, nullptr}};
        gemm_tc_kernel<false><<<dim3(50, 8, 1), 128>>>(gx1, s);
    }
    {
        GemmSet s = {{Wk_c, Wv_c, nullptr}, {bk_c, bv_c, nullptr},
                     {nullptr, nullptr, nullptr}, {gk, gv, nullptr}};
        gemm_tc_kernel<false><<<dim3(192, 8, 2), 128>>>(cross, s);
    }
    attn_kernel<96><<<128 * 8, 256>>>(gq, gk, gv, gctx);
    {
        GemmSet s = {{Wo_c, nullptr, nullptr}, {bo_c, nullptr, nullptr},
                     {gx1, nullptr, nullptr}, {gtmp, nullptr, nullptr}};
        gemm_tc_kernel<false><<<dim3(50, 8, 1), 128>>>(gctx, s);
    }
    ln_kernel<<<M1 / 8, 256>>>(gtmp, g2, b2, gx2, M1);

    // ---- LSTM wavefront over feature axis ----
    transpose_in_kernel<<<dim3(16, 4, 25), dim3(32, 8)>>>(gx2, gY);
    lstm_wave_kernel<<<128, 288>>>(W_ih, W_hh, b_ih, b_hh);

    // ---- pointwise conv + residual + final LN ----
    transpose_out_kernel<<<dim3(16, 4, 25), dim3(32, 8)>>>(gY + 32ull * YSTRIDE, gyt);
    {
        GemmSet s = {{Wc, nullptr, nullptr}, {bc, nullptr, nullptr},
                     {gx2, nullptr, nullptr}, {gtmp, nullptr, nullptr}};
        gemm_tc_kernel<true><<<dim3(50, 8, 1), 128>>>(gyt, s);
    }
    ln_kernel<<<M1 / 8, 256>>>(gtmp, g3, b3, out, M1);
}

// round 15
// speedup vs baseline: 1.1992x; 1.0389x over previous
#include <cuda_runtime.h>
#include <cstddef>

#define DEVF __device__ __forceinline__
typedef unsigned long long ull;

// ---------------- scratch (device globals; no allocations allowed) ----------
__device__ float g_q  [3200 * 512];
__device__ float g_k  [12288 * 512];
__device__ float g_v  [12288 * 512];
__device__ float g_ctx[3200 * 512];
__device__ float g_x1 [3200 * 512];
__device__ float g_x2 [3200 * 512];
__device__ float g_tmp[3200 * 512];
__device__ float g_yt [3200 * 512];

// LSTM wavefront buffers: Y[l][t][k][b], l = 0..32, t<512, k<25, b<128
#define YSTRIDE 1638400   // 512*25*128
__device__ float g_Y[33ull * YSTRIDE];
__device__ int   g_flags[33 * 4 * 32];   // (layer,chunk) progress, 128B padded

// ---------------- activations ------------------------------------------------
DEVF float tanh_fast(float x) {
    float y; asm("tanh.approx.f32 %0, %1;" : "=f"(y) : "f"(x)); return y;
}
DEVF float sig_fast(float x) { return fmaf(tanh_fast(0.5f * x), 0.5f, 0.5f); }

// ---------------- tf32 helpers -----------------------------------------------
DEVF unsigned totf(float x) {
    unsigned r; asm("cvt.rna.tf32.f32 %0, %1;" : "=r"(r) : "f"(x)); return r;
}
DEVF void mma_tf32(float* c, const unsigned* a, unsigned b0, unsigned b1) {
    asm("mma.sync.aligned.m16n8k8.row.col.f32.tf32.tf32.f32 "
        "{%0,%1,%2,%3}, {%4,%5,%6,%7}, {%8,%9}, {%0,%1,%2,%3};"
        : "+f"(c[0]), "+f"(c[1]), "+f"(c[2]), "+f"(c[3])
        : "r"(a[0]), "r"(a[1]), "r"(a[2]), "r"(a[3]), "r"(b0), "r"(b1));
}

DEVF void cpasync16(unsigned dst, const void* src) {
    asm volatile("cp.async.cg.shared.global [%0], [%1], 16;" :: "r"(dst), "l"(src));
}
DEVF void cpasync4(unsigned dst, const void* src) {
    asm volatile("cp.async.ca.shared.global [%0], [%1], 4;" :: "r"(dst), "l"(src));
}
DEVF void cp_commit() { asm volatile("cp.async.commit_group;"); }
DEVF void cp_wait2()  { asm volatile("cp.async.wait_group 2;"); }
DEVF void cp_wait1()  { asm volatile("cp.async.wait_group 1;"); }
DEVF void cp_wait0()  { asm volatile("cp.async.wait_group 0;"); }

// ---------------- tf32 tensor-core GEMM, cp.async 4-stage, BK=16 -------------
// C[.,512] = A[.,512] @ W (+bias)(+res). TRANSW: W stored [N,K] else [K,N].
#define ASTR 20
#define AWRD (64 * ASTR)       // 1280
#define BWRD 1296              // >= max(16*72, 64*20)
template<bool TRANSW>
DEVF void gemm_tc_core(const float* __restrict__ A, const float* __restrict__ W,
                       const float* __restrict__ bias, const float* __restrict__ res,
                       float* __restrict__ C)
{
    __shared__ __align__(16) float As[4][AWRD];
    __shared__ __align__(16) float Bsm[4][BWRD];

    int tid = threadIdx.x;
    int bm = blockIdx.x * 64, bn = blockIdx.y * 64;
    int lane = tid & 31, wid = tid >> 5;
    int wm = wid & 1, wn = wid >> 1;
    int g = lane >> 2, tg = lane & 3;

    float acc[2][4][4];
    #pragma unroll
    for (int i = 0; i < 2; i++)
        #pragma unroll
        for (int j = 0; j < 4; j++)
            #pragma unroll
            for (int q = 0; q < 4; q++) acc[i][j][q] = 0.f;

    int ar = tid >> 1, ac = (tid & 1) * 8;
    const float* Asrc = A + (size_t)(bm + ar) * 512 + ac;
    int kk = tid >> 3, nn = (tid & 7) * 8;
    int nr = tid >> 1, kc = (tid & 1) * 8;
    const float* Bsrc = TRANSW ? (W + (size_t)(bn + nr) * 512 + kc)
                               : (W + (size_t)kk * 512 + bn + nn);

    unsigned asb = (unsigned)__cvta_generic_to_shared(&As[0][0]);
    unsigned bsb = (unsigned)__cvta_generic_to_shared(&Bsm[0][0]);
    unsigned adst = asb + (ar * ASTR + ac) * 4;
    unsigned bdst = bsb + (TRANSW ? (nr * ASTR + kc) : (kk * 72 + nn)) * 4;

    #pragma unroll
    for (int p = 0; p < 3; p++) {
        int k0 = p * 16;
        cpasync16(adst + p * AWRD * 4, Asrc + k0);
        cpasync16(adst + p * AWRD * 4 + 16, Asrc + k0 + 4);
        const float* bs = TRANSW ? (Bsrc + k0) : (Bsrc + (size_t)k0 * 512);
        cpasync16(bdst + p * BWRD * 4, bs);
        cpasync16(bdst + p * BWRD * 4 + 16, bs + 4);
        cp_commit();
    }

    int am0 = wm * 32 + g;

    for (int it = 0; it < 32; it++) {
        int st = it & 3;
        cp_wait2();
        __syncthreads();
        if (it + 3 < 32) {
            int tl = it + 3, ns = tl & 3;
            int k0 = tl * 16;
            cpasync16(adst + ns * AWRD * 4, Asrc + k0);
            cpasync16(adst + ns * AWRD * 4 + 16, Asrc + k0 + 4);
            const float* bs = TRANSW ? (Bsrc + k0) : (Bsrc + (size_t)k0 * 512);
            cpasync16(bdst + ns * BWRD * 4, bs);
            cpasync16(bdst + ns * BWRD * 4 + 16, bs + 4);
        }
        cp_commit();

        const unsigned* Au = (const unsigned*)As[st];
        const unsigned* Bu = (const unsigned*)Bsm[st];
        #pragma unroll
        for (int ks = 0; ks < 2; ks++) {
            int klo = ks * 8 + tg;
            unsigned afr[2][4];
            #pragma unroll
            for (int mf = 0; mf < 2; mf++) {
                int m = am0 + mf * 16;
                afr[mf][0] = Au[m * ASTR + klo];
                afr[mf][1] = Au[(m + 8) * ASTR + klo];
                afr[mf][2] = Au[m * ASTR + klo + 4];
                afr[mf][3] = Au[(m + 8) * ASTR + klo + 4];
            }
            #pragma unroll
            for (int nf = 0; nf < 4; nf++) {
                int col = wn * 32 + nf * 8 + g;
                unsigned b0, b1;
                if (!TRANSW) {
                    b0 = Bu[klo * 72 + col];
                    b1 = Bu[(klo + 4) * 72 + col];
                } else {
                    b0 = Bu[col * ASTR + klo];
                    b1 = Bu[col * ASTR + klo + 4];
                }
                mma_tf32(acc[0][nf], afr[0], b0, b1);
                mma_tf32(acc[1][nf], afr[1], b0, b1);
            }
        }
    }

    #pragma unroll
    for (int nf = 0; nf < 4; nf++) {
        int col = bn + wn * 32 + nf * 8 + 2 * tg;
        float2 bv = *(const float2*)(bias + col);
        #pragma unroll
        for (int mf = 0; mf < 2; mf++) {
            int row = bm + wm * 32 + mf * 16 + g;
            float2 v0 = make_float2(acc[mf][nf][0] + bv.x, acc[mf][nf][1] + bv.y);
            float2 v1 = make_float2(acc[mf][nf][2] + bv.x, acc[mf][nf][3] + bv.y);
            if (res) {
                float2 r0 = *(const float2*)(res + (size_t)row * 512 + col);
                float2 r1 = *(const float2*)(res + (size_t)(row + 8) * 512 + col);
                v0.x += r0.x; v0.y += r0.y; v1.x += r1.x; v1.y += r1.y;
            }
            *(float2*)(C + (size_t)row * 512 + col) = v0;
            *(float2*)(C + (size_t)(row + 8) * 512 + col) = v1;
        }
    }
}

struct GemmSet {
    const float* W[3];
    const float* b[3];
    const float* r[3];
    float*       C[3];
};

template<bool TRANSW>
__global__ void __launch_bounds__(128, 5) gemm_tc_kernel(const float* __restrict__ A, GemmSet s) {
    int z = blockIdx.z;
    gemm_tc_core<TRANSW>(A, s.W[z], s.b[z], s.r[z], s.C[z]);
}

// ---------------- attention core: one block per (b, h), 256 threads ---------
template<int S>
__global__ void __launch_bounds__(256) attn_kernel(
    const float* __restrict__ Q, const float* __restrict__ Kp,
    const float* __restrict__ Vp, float* __restrict__ O)
{
    __shared__ float qs[25 * 64];
    __shared__ __align__(16) float kv[96 * 64];
    __shared__ float sc[25 * S];
    int b = blockIdx.x >> 3, h = blockIdx.x & 7;
    int tid = threadIdx.x;
    const float scale = 0.125f;
    size_t qbase = (size_t)b * 25 * 512 + h * 64;
    size_t kbase = (size_t)b * S  * 512 + h * 64;

    for (int i = tid; i < 25 * 64; i += 256) qs[i] = Q[qbase + (size_t)(i >> 6) * 512 + (i & 63)];
    for (int i = tid; i < S  * 64; i += 256) kv[i] = Kp[kbase + (size_t)(i >> 6) * 512 + (i & 63)];
    __syncthreads();

    for (int i = tid; i < 25 * S; i += 256) {
        int l = i / S, s = i - l * S;
        float acc = 0.f;
        #pragma unroll
        for (int e4 = 0; e4 < 16; e4++) {
            float4 q4 = *(const float4*)&qs[l * 64 + e4 * 4];
            float4 k4 = *(const float4*)&kv[s * 64 + e4 * 4];
            acc += q4.x * k4.x + q4.y * k4.y + q4.z * k4.z + q4.w * k4.w;
        }
        sc[i] = acc * scale;
    }
    __syncthreads();

    int warp = tid >> 5, lane = tid & 31;
    for (int l = warp; l < 25; l += 8) {
        float mx = -1e30f;
        for (int s = lane; s < S; s += 32) mx = fmaxf(mx, sc[l * S + s]);
        #pragma unroll
        for (int o = 16; o; o >>= 1) mx = fmaxf(mx, __shfl_xor_sync(~0u, mx, o));
        float sum = 0.f;
        for (int s = lane; s < S; s += 32) {
            float e = __expf(sc[l * S + s] - mx);
            sc[l * S + s] = e; sum += e;
        }
        #pragma unroll
        for (int o = 16; o; o >>= 1) sum += __shfl_xor_sync(~0u, sum, o);
        float inv = __fdividef(1.f, sum);
        for (int s = lane; s < S; s += 32) sc[l * S + s] *= inv;
    }
    __syncthreads();

    for (int i = tid; i < S * 64; i += 256) kv[i] = Vp[kbase + (size_t)(i >> 6) * 512 + (i & 63)];
    __syncthreads();

    for (int i = tid; i < 25 * 16; i += 256) {
        int l = i >> 4, e4 = (i & 15) * 4;
        float4 acc = make_float4(0.f, 0.f, 0.f, 0.f);
        const float* scl = &sc[l * S];
        #pragma unroll 4
        for (int s = 0; s < S; s++) {
            float w = scl[s];
            float4 v4 = *(const float4*)&kv[s * 64 + e4];
            acc.x += w * v4.x; acc.y += w * v4.y;
            acc.z += w * v4.z; acc.w += w * v4.w;
        }
        *(float4*)(&O[qbase + (size_t)l * 512 + e4]) = acc;
    }
}

// ---------------- LayerNorm over rows of 512 (warp per row) ------------------
__global__ void __launch_bounds__(256) ln_kernel(
    const float* __restrict__ in, const float* __restrict__ g,
    const float* __restrict__ bb, float* __restrict__ out, int M)
{
    int row = blockIdx.x * 8 + (threadIdx.x >> 5);
    int lane = threadIdx.x & 31;
    if (row >= M) return;
    const float* p = in + (size_t)row * 512;
    float v[16];
    float s = 0.f, s2 = 0.f;
    #pragma unroll
    for (int i = 0; i < 16; i++) {
        v[i] = p[lane + 32 * i];
        s += v[i]; s2 += v[i] * v[i];
    }
    #pragma unroll
    for (int o = 16; o; o >>= 1) {
        s  += __shfl_xor_sync(~0u, s,  o);
        s2 += __shfl_xor_sync(~0u, s2, o);
    }
    float mean = s * (1.f / 512.f);
    float var  = s2 * (1.f / 512.f) - mean * mean;
    float rstd = rsqrtf(var + 1e-5f);
    float* q = out + (size_t)row * 512;
    #pragma unroll
    for (int i = 0; i < 16; i++) {
        int d = lane + 32 * i;
        q[d] = (v[i] - mean) * rstd * g[d] + bb[d];
    }
}

// ---------------- tiled transposes -------------------------------------------
__global__ void transpose_in_kernel(const float* __restrict__ in, float* __restrict__ out) {
    __shared__ float tile[32][33];
    int tx = threadIdx.x, ty = threadIdx.y;
    int t0 = blockIdx.x * 32, b0 = blockIdx.y * 32, k = blockIdx.z;
    #pragma unroll
    for (int i = 0; i < 4; i++)
        tile[ty + 8 * i][tx] = in[(size_t)(b0 + ty + 8 * i) * 12800 + k * 512 + t0 + tx];
    __syncthreads();
    #pragma unroll
    for (int i = 0; i < 4; i++)
        out[(size_t)(t0 + ty + 8 * i) * 3200 + k * 128 + b0 + tx] = tile[tx][ty + 8 * i];
}
__global__ void transpose_out_kernel(const float* __restrict__ in, float* __restrict__ out) {
    __shared__ float tile[32][33];
    int tx = threadIdx.x, ty = threadIdx.y;
    int c0 = blockIdx.x * 32, b0 = blockIdx.y * 32, l = blockIdx.z;
    #pragma unroll
    for (int i = 0; i < 4; i++)
        tile[ty + 8 * i][tx] = in[(size_t)(c0 + ty + 8 * i) * 3200 + l * 128 + b0 + tx];
    __syncthreads();
    #pragma unroll
    for (int i = 0; i < 4; i++)
        out[(size_t)((b0 + ty + 8 * i) * 25 + l) * 512 + c0 + tx] = tile[tx][ty + 8 * i];
}

__global__ void zero_flags_kernel() {
    int i = blockIdx.x * 256 + threadIdx.x;
    if (i < 33 * 4 * 32) g_flags[i] = 0;
}

DEVF void spinwait(const int* p, int need) {
    int v;
    do {
        asm volatile("ld.acquire.gpu.global.b32 %0, [%1];" : "=r"(v) : "l"(p) : "memory");
    } while (v < need);
}

// ---------------- tensor-core LSTM wavefront, 16 compute warps ---------------
// 128 blocks = 32 layers x 4 chunks(32 batches). 544 threads = 17 warps:
// warps 0-15 compute (warp w: unit group w&3, batch quarter w>>2 -> 1 nf),
// warp 16 = IO (cached flag + cp.async x prefetch). 4-slot rotation, lag 2:
// step t reads slot t&3, h_t -> slot (t+1)&3, x_{t+2} -> slot (t+2)&3.
#define BROWS 56
#define BSTR  40
__global__ void __launch_bounds__(544, 1) lstm_wave_kernel(
    const float* __restrict__ Wih, const float* __restrict__ Whh,
    const float* __restrict__ bih, const float* __restrict__ bhh)
{
    __shared__ __align__(16) unsigned Bsm[4][BROWS][BSTR];

    int layer = blockIdx.x & 31;
    int chunk = blockIdx.x >> 5;
    int b0 = chunk * 32;
    const float* in  = g_Y + (size_t)layer * YSTRIDE;
    float* outp      = g_Y + (size_t)(layer + 1) * YSTRIDE;
    const int* inflag = g_flags + (layer * 4 + chunk) * 32;
    int* outflag      = g_flags + ((layer + 1) * 4 + chunk) * 32;

    int tid = threadIdx.x;
    int warp = tid >> 5, lane = tid & 31;
    int g = lane >> 2, tg = lane & 3;

    for (int i = tid; i < 4 * BROWS * BSTR; i += 544) ((unsigned*)Bsm)[i] = 0;

    bool isComp = (warp < 16);
    int pair = warp & 3;          // unit group
    int nf   = warp >> 2;         // batch quarter (n fragment)
    int u = pair * 8 + g;
    bool valid = isComp && (u < 25);

    unsigned afr[2][7][4];
    float bias_i = 0.f, bias_f = 0.f, bias_g = 0.f, bias_o = 0.f;
    if (isComp) {
        const float* WI = Wih + (size_t)layer * 2500;
        const float* WH = Whh + (size_t)layer * 2500;
        #pragma unroll
        for (int T = 0; T < 2; T++) {
            int rowA = (T == 0 ? 0 : 50) + u;
            int rowB = (T == 0 ? 25 : 75) + u;
            #pragma unroll
            for (int ks = 0; ks < 7; ks++) {
                #pragma unroll
                for (int q = 0; q < 4; q++) {
                    int k = ks * 8 + tg + (q >= 2 ? 4 : 0);
                    int row = (q & 1) ? rowB : rowA;
                    float w = 0.f;
                    if (valid) {
                        if (k < 25)      w = WI[row * 25 + k];
                        else if (k < 50) w = WH[row * 25 + (k - 25)];
                    }
                    afr[T][ks][q] = totf(w);
                }
            }
        }
        if (valid) {
            bias_i = bih[layer * 100 + u]      + bhh[layer * 100 + u];
            bias_f = bih[layer * 100 + 25 + u] + bhh[layer * 100 + 25 + u];
            bias_g = bih[layer * 100 + 50 + u] + bhh[layer * 100 + 50 + u];
            bias_o = bih[layer * 100 + 75 + u] + bhh[layer * 100 + 75 + u];
        }
    }
    float c0s = 0.f, c1s = 0.f;
    __syncthreads();

    unsigned bsmb = (unsigned)__cvta_generic_to_shared(&Bsm[0][0][0]);

    // prologue: x_0 -> slot0, x_1 -> slot1 (raw fp32 bits)
    if (warp == 16) {
        if (layer > 0 && lane == 0) spinwait(inflag, 2);
        __syncwarp();
        #pragma unroll
        for (int p = 0; p < 2; p++) {
            const float* src = in + (size_t)p * 3200 + b0;
            #pragma unroll
            for (int k = 0; k < 25; k++)
                Bsm[p][k][lane] = __float_as_uint(src[k * 128 + lane]);
        }
    }
    __syncthreads();

    int cached = 2;
    for (int t = 0; t < 512; t++) {
        int s = t & 3;
        if (isComp) {
            float acc0[4], acc1[4];
            acc0[0] = bias_i; acc0[1] = bias_i;
            acc0[2] = bias_f; acc0[3] = bias_f;
            acc1[0] = bias_g; acc1[1] = bias_g;
            acc1[2] = bias_o; acc1[3] = bias_o;
            const unsigned* Bp = &Bsm[s][0][0];
            #pragma unroll
            for (int ks = 0; ks < 7; ks++) {
                int r0 = (ks * 8 + tg) * BSTR;
                unsigned b0v = Bp[r0 + nf * 8 + g];
                unsigned b1v = Bp[r0 + 4 * BSTR + nf * 8 + g];
                mma_tf32(acc0, afr[0][ks], b0v, b1v);
                mma_tf32(acc1, afr[1][ks], b0v, b1v);
            }
            unsigned* Bn = &Bsm[(t + 1) & 3][0][0];
            float i0 = sig_fast(acc0[0]),  i1 = sig_fast(acc0[1]);
            float f0 = sig_fast(acc0[2]),  f1 = sig_fast(acc0[3]);
            float q0 = tanh_fast(acc1[0]), q1 = tanh_fast(acc1[1]);
            float o0 = sig_fast(acc1[2]),  o1 = sig_fast(acc1[3]);
            c0s = f0 * c0s + i0 * q0;
            c1s = f1 * c1s + i1 * q1;
            float h0 = o0 * tanh_fast(c0s);
            float h1 = o1 * tanh_fast(c1s);
            if (valid) {
                uint2 hp = make_uint2(__float_as_uint(h0), __float_as_uint(h1));
                *(uint2*)&Bn[(25 + u) * BSTR + nf * 8 + 2 * tg] = hp;
                *(float2*)(outp + (size_t)t * 3200 + u * 128 + b0 + nf * 8 + 2 * tg)
                    = make_float2(h0, h1);
            }
        } else {
            if (t < 510) {
                if (layer > 0 && lane == 0) {
                    int need = t + 3;
                    if (cached < need) {
                        int v;
                        do {
                            asm volatile("ld.acquire.gpu.global.b32 %0, [%1];" : "=r"(v) : "l"(inflag) : "memory");
                        } while (v < need);
                        cached = v;
                    }
                }
                __syncwarp();
                const float* src = in + (size_t)(t + 2) * 3200 + b0 + lane;
                unsigned dst = bsmb + ((((t + 2) & 3) * BROWS) * BSTR + lane) * 4;
                #pragma unroll
                for (int k = 0; k < 25; k++)
                    cpasync4(dst + k * BSTR * 4, src + k * 128);
                cp_commit();
                cp_wait1();
            } else {
                cp_wait0();
            }
        }
        __syncthreads();
        if (tid == 0) {
            int nv = t + 1;
            asm volatile("st.release.gpu.global.b32 [%0], %1;" :: "l"(outflag), "r"(nv) : "memory");
        }
    }
}

// ---------------- launcher ---------------------------------------------------
extern "C" void kernel_launch(void* const* d_in, const int* in_sizes, int n_in,
                              void* d_out, int out_size)
{
    const float* x     = (const float*)d_in[0];
    const float* cross = (const float*)d_in[1];
    const float* Wq_s = (const float*)d_in[2];  const float* bq_s = (const float*)d_in[3];
    const float* Wk_s = (const float*)d_in[4];  const float* bk_s = (const float*)d_in[5];
    const float* Wv_s = (const float*)d_in[6];  const float* bv_s = (const float*)d_in[7];
    const float* Wo_s = (const float*)d_in[8];  const float* bo_s = (const float*)d_in[9];
    const float* Wq_c = (const float*)d_in[10]; const float* bq_c = (const float*)d_in[11];
    const float* Wk_c = (const float*)d_in[12]; const float* bk_c = (const float*)d_in[13];
    const float* Wv_c = (const float*)d_in[14]; const float* bv_c = (const float*)d_in[15];
    const float* Wo_c = (const float*)d_in[16]; const float* bo_c = (const float*)d_in[17];
    const float* g1 = (const float*)d_in[18]; const float* b1 = (const float*)d_in[19];
    const float* g2 = (const float*)d_in[20]; const float* b2 = (const float*)d_in[21];
    const float* g3 = (const float*)d_in[22]; const float* b3 = (const float*)d_in[23];
    const float* W_ih = (const float*)d_in[24];
    const float* W_hh = (const float*)d_in[25];
    const float* b_ih = (const float*)d_in[26];
    const float* b_hh = (const float*)d_in[27];
    const float* Wc = (const float*)d_in[28]; const float* bc = (const float*)d_in[29];
    float* out = (float*)d_out;

    float *gq, *gk, *gv, *gctx, *gx1, *gx2, *gtmp, *gyt, *gY;
    cudaGetSymbolAddress((void**)&gq,   g_q);
    cudaGetSymbolAddress((void**)&gk,   g_k);
    cudaGetSymbolAddress((void**)&gv,   g_v);
    cudaGetSymbolAddress((void**)&gctx, g_ctx);
    cudaGetSymbolAddress((void**)&gx1,  g_x1);
    cudaGetSymbolAddress((void**)&gx2,  g_x2);
    cudaGetSymbolAddress((void**)&gtmp, g_tmp);
    cudaGetSymbolAddress((void**)&gyt,  g_yt);
    cudaGetSymbolAddress((void**)&gY,   g_Y);

    const int M1 = 3200;    // B*L
    zero_flags_kernel<<<17, 256>>>();

    // ---- self attention ----
    {
        GemmSet s = {{Wq_s, Wk_s, Wv_s}, {bq_s, bk_s, bv_s},
                     {nullptr, nullptr, nullptr}, {gq, gk, gv}};
        gemm_tc_kernel<false><<<dim3(50, 8, 3), 128>>>(x, s);
    }
    attn_kernel<25><<<128 * 8, 256>>>(gq, gk, gv, gctx);
    {
        GemmSet s = {{Wo_s, nullptr, nullptr}, {bo_s, nullptr, nullptr},
                     {x, nullptr, nullptr}, {gtmp, nullptr, nullptr}};
        gemm_tc_kernel<false><<<dim3(50, 8, 1), 128>>>(gctx, s);
    }
    ln_kernel<<<M1 / 8, 256>>>(gtmp, g1, b1, gx1, M1);

    // ---- cross attention ----
    {
        GemmSet s = {{Wq_c, nullptr, nullptr}, {bq_c, nullptr, nullptr},
                     {nullptr, nullptr, nullptr}, {gq, nullptr, nullptr}};
        gemm_tc_kernel<false><<<dim3(50, 8, 1), 128>>>(gx1, s);
    }
    {
        GemmSet s = {{Wk_c, Wv_c, nullptr}, {bk_c, bv_c, nullptr},
                     {nullptr, nullptr, nullptr}, {gk, gv, nullptr}};
        gemm_tc_kernel<false><<<dim3(192, 8, 2), 128>>>(cross, s);
    }
    attn_kernel<96><<<128 * 8, 256>>>(gq, gk, gv, gctx);
    {
        GemmSet s = {{Wo_c, nullptr, nullptr}, {bo_c, nullptr, nullptr},
                     {gx1, nullptr, nullptr}, {gtmp, nullptr, nullptr}};
        gemm_tc_kernel<false><<<dim3(50, 8, 1), 128>>>(gctx, s);
    }
    ln_kernel<<<M1 / 8, 256>>>(gtmp, g2, b2, gx2, M1);

    // ---- LSTM wavefront over feature axis ----
    transpose_in_kernel<<<dim3(16, 4, 25), dim3(32, 8)>>>(gx2, gY);
    lstm_wave_kernel<<<128, 544>>>(W_ih, W_hh, b_ih, b_hh);

    // ---- pointwise conv + residual + final LN ----
    transpose_out_kernel<<<dim3(16, 4, 25), dim3(32, 8)>>>(gY + 32ull * YSTRIDE, gyt);
    {
        GemmSet s = {{Wc, nullptr, nullptr}, {bc, nullptr, nullptr},
                     {gx2, nullptr, nullptr}, {gtmp, nullptr, nullptr}};
        gemm_tc_kernel<true><<<dim3(50, 8, 1), 128>>>(gyt, s);
    }
    ln_kernel<<<M1 / 8, 256>>>(gtmp, g3, b3, out, M1);
}

// round 16
// speedup vs baseline: 1.2293x; 1.0251x over previous
#include <cuda_runtime.h>
#include <cstddef>

#define DEVF __device__ __forceinline__
typedef unsigned long long ull;

// ---------------- scratch (device globals; no allocations allowed) ----------
__device__ float g_q  [3200 * 512];
__device__ float g_k  [3200 * 512];
__device__ float g_v  [3200 * 512];
__device__ float g_kc [12288 * 512];
__device__ float g_vc [12288 * 512];
__device__ float g_ctx[3200 * 512];
__device__ float g_x1 [3200 * 512];
__device__ float g_x2 [3200 * 512];
__device__ float g_tmp[3200 * 512];
__device__ float g_yt [3200 * 512];

// LSTM wavefront buffers: Y[l][t][k][b], l = 0..32, t<512, k<25, b<128
#define YSTRIDE 1638400   // 512*25*128
__device__ float g_Y[33ull * YSTRIDE];
__device__ int   g_flags[33 * 4 * 32];   // (layer,chunk) progress, 128B padded

// ---------------- activations ------------------------------------------------
DEVF float tanh_fast(float x) {
    float y; asm("tanh.approx.f32 %0, %1;" : "=f"(y) : "f"(x)); return y;
}
DEVF float sig_fast(float x) { return fmaf(tanh_fast(0.5f * x), 0.5f, 0.5f); }

// ---------------- tf32 helpers -----------------------------------------------
DEVF unsigned totf(float x) {
    unsigned r; asm("cvt.rna.tf32.f32 %0, %1;" : "=r"(r) : "f"(x)); return r;
}
DEVF void mma_tf32(float* c, const unsigned* a, unsigned b0, unsigned b1) {
    asm("mma.sync.aligned.m16n8k8.row.col.f32.tf32.tf32.f32 "
        "{%0,%1,%2,%3}, {%4,%5,%6,%7}, {%8,%9}, {%0,%1,%2,%3};"
        : "+f"(c[0]), "+f"(c[1]), "+f"(c[2]), "+f"(c[3])
        : "r"(a[0]), "r"(a[1]), "r"(a[2]), "r"(a[3]), "r"(b0), "r"(b1));
}

DEVF void cpasync16(unsigned dst, const void* src) {
    asm volatile("cp.async.cg.shared.global [%0], [%1], 16;" :: "r"(dst), "l"(src));
}
DEVF void cpasync4(unsigned dst, const void* src) {
    asm volatile("cp.async.ca.shared.global [%0], [%1], 4;" :: "r"(dst), "l"(src));
}
DEVF void cp_commit() { asm volatile("cp.async.commit_group;"); }
DEVF void cp_wait2()  { asm volatile("cp.async.wait_group 2;"); }
DEVF void cp_wait1()  { asm volatile("cp.async.wait_group 1;"); }
DEVF void cp_wait0()  { asm volatile("cp.async.wait_group 0;"); }

// ================= 64x64 GEMM (singles), cp.async 4-stage, BK=16 =============
#define ASTR 20
#define AWRD (64 * ASTR)       // 1280
#define BWRD 1296
template<bool TRANSW>
DEVF void gemm_tc_core(const float* __restrict__ A, const float* __restrict__ W,
                       const float* __restrict__ bias, const float* __restrict__ res,
                       float* __restrict__ C)
{
    __shared__ __align__(16) float As[4][AWRD];
    __shared__ __align__(16) float Bsm[4][BWRD];

    int tid = threadIdx.x;
    int bm = blockIdx.x * 64, bn = blockIdx.y * 64;
    int lane = tid & 31, wid = tid >> 5;
    int wm = wid & 1, wn = wid >> 1;
    int g = lane >> 2, tg = lane & 3;

    float acc[2][4][4];
    #pragma unroll
    for (int i = 0; i < 2; i++)
        #pragma unroll
        for (int j = 0; j < 4; j++)
            #pragma unroll
            for (int q = 0; q < 4; q++) acc[i][j][q] = 0.f;

    int ar = tid >> 1, ac = (tid & 1) * 8;
    const float* Asrc = A + (size_t)(bm + ar) * 512 + ac;
    int kk = tid >> 3, nn = (tid & 7) * 8;
    int nr = tid >> 1, kc = (tid & 1) * 8;
    const float* Bsrc = TRANSW ? (W + (size_t)(bn + nr) * 512 + kc)
                               : (W + (size_t)kk * 512 + bn + nn);

    unsigned asb = (unsigned)__cvta_generic_to_shared(&As[0][0]);
    unsigned bsb = (unsigned)__cvta_generic_to_shared(&Bsm[0][0]);
    unsigned adst = asb + (ar * ASTR + ac) * 4;
    unsigned bdst = bsb + (TRANSW ? (nr * ASTR + kc) : (kk * 72 + nn)) * 4;

    #pragma unroll
    for (int p = 0; p < 3; p++) {
        int k0 = p * 16;
        cpasync16(adst + p * AWRD * 4, Asrc + k0);
        cpasync16(adst + p * AWRD * 4 + 16, Asrc + k0 + 4);
        const float* bs = TRANSW ? (Bsrc + k0) : (Bsrc + (size_t)k0 * 512);
        cpasync16(bdst + p * BWRD * 4, bs);
        cpasync16(bdst + p * BWRD * 4 + 16, bs + 4);
        cp_commit();
    }

    int am0 = wm * 32 + g;

    for (int it = 0; it < 32; it++) {
        int st = it & 3;
        cp_wait2();
        __syncthreads();
        if (it + 3 < 32) {
            int tl = it + 3, ns = tl & 3;
            int k0 = tl * 16;
            cpasync16(adst + ns * AWRD * 4, Asrc + k0);
            cpasync16(adst + ns * AWRD * 4 + 16, Asrc + k0 + 4);
            const float* bs = TRANSW ? (Bsrc + k0) : (Bsrc + (size_t)k0 * 512);
            cpasync16(bdst + ns * BWRD * 4, bs);
            cpasync16(bdst + ns * BWRD * 4 + 16, bs + 4);
        }
        cp_commit();

        const unsigned* Au = (const unsigned*)As[st];
        const unsigned* Bu = (const unsigned*)Bsm[st];
        #pragma unroll
        for (int ks = 0; ks < 2; ks++) {
            int klo = ks * 8 + tg;
            unsigned afr[2][4];
            #pragma unroll
            for (int mf = 0; mf < 2; mf++) {
                int m = am0 + mf * 16;
                afr[mf][0] = Au[m * ASTR + klo];
                afr[mf][1] = Au[(m + 8) * ASTR + klo];
                afr[mf][2] = Au[m * ASTR + klo + 4];
                afr[mf][3] = Au[(m + 8) * ASTR + klo + 4];
            }
            #pragma unroll
            for (int nf = 0; nf < 4; nf++) {
                int col = wn * 32 + nf * 8 + g;
                unsigned b0, b1;
                if (!TRANSW) {
                    b0 = Bu[klo * 72 + col];
                    b1 = Bu[(klo + 4) * 72 + col];
                } else {
                    b0 = Bu[col * ASTR + klo];
                    b1 = Bu[col * ASTR + klo + 4];
                }
                mma_tf32(acc[0][nf], afr[0], b0, b1);
                mma_tf32(acc[1][nf], afr[1], b0, b1);
            }
        }
    }

    #pragma unroll
    for (int nf = 0; nf < 4; nf++) {
        int col = bn + wn * 32 + nf * 8 + 2 * tg;
        float2 bv = *(const float2*)(bias + col);
        #pragma unroll
        for (int mf = 0; mf < 2; mf++) {
            int row = bm + wm * 32 + mf * 16 + g;
            float2 v0 = make_float2(acc[mf][nf][0] + bv.x, acc[mf][nf][1] + bv.y);
            float2 v1 = make_float2(acc[mf][nf][2] + bv.x, acc[mf][nf][3] + bv.y);
            if (res) {
                float2 r0 = *(const float2*)(res + (size_t)row * 512 + col);
                float2 r1 = *(const float2*)(res + (size_t)(row + 8) * 512 + col);
                v0.x += r0.x; v0.y += r0.y; v1.x += r1.x; v1.y += r1.y;
            }
            *(float2*)(C + (size_t)row * 512 + col) = v0;
            *(float2*)(C + (size_t)(row + 8) * 512 + col) = v1;
        }
    }
}

struct GemmSet {
    const float* W[3];
    const float* b[3];
    const float* r[3];
    float*       C[3];
};

template<bool TRANSW>
__global__ void __launch_bounds__(128, 5) gemm_tc_kernel(const float* __restrict__ A, GemmSet s) {
    int z = blockIdx.z;
    gemm_tc_core<TRANSW>(A, s.W[z], s.b[z], s.r[z], s.C[z]);
}

// ================= 128x128 GEMM (merged launch), BK=8, 3-stage ===============
// 256 threads = 2(m)x4(n) warps, warp tile 64x32. Traffic-optimal (L2-BW bound).
#define G2ASTR 12
#define G2AWRD (128 * G2ASTR)      // 1536
#define G2BSTR 136
#define G2BWRD 1536                // covers 8*136=1088
struct Gemm5 {
    const float* A[5]; const float* W[5]; const float* bias[5];
    float* C[5]; int M[5];
};
__global__ void __launch_bounds__(256) gemm128_kernel(Gemm5 s)
{
    __shared__ __align__(16) float As[3][G2AWRD];
    __shared__ __align__(16) float Bsm[3][G2BWRD];

    int z = blockIdx.z;
    const float* A = s.A[z];
    const float* W = s.W[z];
    int M = s.M[z];
    int bm = blockIdx.x * 128, bn = blockIdx.y * 128;
    if (bm >= M) return;

    int tid = threadIdx.x;
    int lane = tid & 31, wid = tid >> 5;
    int wm = wid & 1, wn = wid >> 1;          // 2 x 4 warps
    int g = lane >> 2, tg = lane & 3;

    float acc[4][4][4];
    #pragma unroll
    for (int i = 0; i < 4; i++)
        #pragma unroll
        for (int j = 0; j < 4; j++)
            #pragma unroll
            for (int q = 0; q < 4; q++) acc[i][j][q] = 0.f;

    int ar = tid >> 1, ac = (tid & 1) * 4;    // A: 128 rows x 8 k
    const float* Asrc = A + (size_t)(bm + ar) * 512 + ac;
    int kk = tid >> 5, nn = (tid & 31) * 4;   // B: 8 rows x 128 cols
    const float* Bsrc = W + (size_t)kk * 512 + bn + nn;

    unsigned asb = (unsigned)__cvta_generic_to_shared(&As[0][0]);
    unsigned bsb = (unsigned)__cvta_generic_to_shared(&Bsm[0][0]);
    unsigned adst = asb + (ar * G2ASTR + ac) * 4;
    unsigned bdst = bsb + (kk * G2BSTR + nn) * 4;

    #pragma unroll
    for (int p = 0; p < 2; p++) {
        int k0 = p * 8;
        cpasync16(adst + p * G2AWRD * 4, Asrc + k0);
        cpasync16(bdst + p * G2BWRD * 4, Bsrc + (size_t)k0 * 512);
        cp_commit();
    }

    int am0 = wm * 64 + g;
    int cn0 = wn * 32 + g;

    for (int it = 0; it < 64; it++) {
        int st = it % 3;
        cp_wait1();
        __syncthreads();
        if (it + 2 < 64) {
            int ns = (it + 2) % 3;
            int k0 = (it + 2) * 8;
            cpasync16(adst + ns * G2AWRD * 4, Asrc + k0);
            cpasync16(bdst + ns * G2BWRD * 4, Bsrc + (size_t)k0 * 512);
        }
        cp_commit();

        const unsigned* Au = (const unsigned*)As[st];
        const unsigned* Bu = (const unsigned*)Bsm[st];
        unsigned afr[4][4];
        #pragma unroll
        for (int mf = 0; mf < 4; mf++) {
            int m = am0 + mf * 16;
            afr[mf][0] = Au[m * G2ASTR + tg];
            afr[mf][1] = Au[(m + 8) * G2ASTR + tg];
            afr[mf][2] = Au[m * G2ASTR + tg + 4];
            afr[mf][3] = Au[(m + 8) * G2ASTR + tg + 4];
        }
        #pragma unroll
        for (int nf = 0; nf < 4; nf++) {
            unsigned b0 = Bu[tg * G2BSTR + cn0 + nf * 8];
            unsigned b1 = Bu[(tg + 4) * G2BSTR + cn0 + nf * 8];
            #pragma unroll
            for (int mf = 0; mf < 4; mf++)
                mma_tf32(acc[mf][nf], afr[mf], b0, b1);
        }
    }

    const float* bias = s.bias[z];
    float* C = s.C[z];
    #pragma unroll
    for (int nf = 0; nf < 4; nf++) {
        int col = bn + wn * 32 + nf * 8 + 2 * tg;
        float2 bv = *(const float2*)(bias + col);
        #pragma unroll
        for (int mf = 0; mf < 4; mf++) {
            int row = bm + wm * 64 + mf * 16 + g;
            float2 v0 = make_float2(acc[mf][nf][0] + bv.x, acc[mf][nf][1] + bv.y);
            float2 v1 = make_float2(acc[mf][nf][2] + bv.x, acc[mf][nf][3] + bv.y);
            *(float2*)(C + (size_t)row * 512 + col) = v0;
            *(float2*)(C + (size_t)(row + 8) * 512 + col) = v1;
        }
    }
}

// ---------------- attention core: one block per (b, h), 256 threads ---------
template<int S>
__global__ void __launch_bounds__(256) attn_kernel(
    const float* __restrict__ Q, const float* __restrict__ Kp,
    const float* __restrict__ Vp, float* __restrict__ O)
{
    __shared__ float qs[25 * 64];
    __shared__ __align__(16) float kv[96 * 64];
    __shared__ float sc[25 * S];
    int b = blockIdx.x >> 3, h = blockIdx.x & 7;
    int tid = threadIdx.x;
    const float scale = 0.125f;
    size_t qbase = (size_t)b * 25 * 512 + h * 64;
    size_t kbase = (size_t)b * S  * 512 + h * 64;

    for (int i = tid; i < 25 * 64; i += 256) qs[i] = Q[qbase + (size_t)(i >> 6) * 512 + (i & 63)];
    for (int i = tid; i < S  * 64; i += 256) kv[i] = Kp[kbase + (size_t)(i >> 6) * 512 + (i & 63)];
    __syncthreads();

    for (int i = tid; i < 25 * S; i += 256) {
        int l = i / S, s = i - l * S;
        float acc = 0.f;
        #pragma unroll
        for (int e4 = 0; e4 < 16; e4++) {
            float4 q4 = *(const float4*)&qs[l * 64 + e4 * 4];
            float4 k4 = *(const float4*)&kv[s * 64 + e4 * 4];
            acc += q4.x * k4.x + q4.y * k4.y + q4.z * k4.z + q4.w * k4.w;
        }
        sc[i] = acc * scale;
    }
    __syncthreads();

    int warp = tid >> 5, lane = tid & 31;
    for (int l = warp; l < 25; l += 8) {
        float mx = -1e30f;
        for (int s = lane; s < S; s += 32) mx = fmaxf(mx, sc[l * S + s]);
        #pragma unroll
        for (int o = 16; o; o >>= 1) mx = fmaxf(mx, __shfl_xor_sync(~0u, mx, o));
        float sum = 0.f;
        for (int s = lane; s < S; s += 32) {
            float e = __expf(sc[l * S + s] - mx);
            sc[l * S + s] = e; sum += e;
        }
        #pragma unroll
        for (int o = 16; o; o >>= 1) sum += __shfl_xor_sync(~0u, sum, o);
        float inv = __fdividef(1.f, sum);
        for (int s = lane; s < S; s += 32) sc[l * S + s] *= inv;
    }
    __syncthreads();

    for (int i = tid; i < S * 64; i += 256) kv[i] = Vp[kbase + (size_t)(i >> 6) * 512 + (i & 63)];
    __syncthreads();

    for (int i = tid; i < 25 * 16; i += 256) {
        int l = i >> 4, e4 = (i & 15) * 4;
        float4 acc = make_float4(0.f, 0.f, 0.f, 0.f);
        const float* scl = &sc[l * S];
        #pragma unroll 4
        for (int s = 0; s < S; s++) {
            float w = scl[s];
            float4 v4 = *(const float4*)&kv[s * 64 + e4];
            acc.x += w * v4.x; acc.y += w * v4.y;
            acc.z += w * v4.z; acc.w += w * v4.w;
        }
        *(float4*)(&O[qbase + (size_t)l * 512 + e4]) = acc;
    }
}

// ---------------- LayerNorm over rows of 512 (warp per row) ------------------
__global__ void __launch_bounds__(256) ln_kernel(
    const float* __restrict__ in, const float* __restrict__ g,
    const float* __restrict__ bb, float* __restrict__ out, int M)
{
    int row = blockIdx.x * 8 + (threadIdx.x >> 5);
    int lane = threadIdx.x & 31;
    if (row >= M) return;
    const float* p = in + (size_t)row * 512;
    float v[16];
    float s = 0.f, s2 = 0.f;
    #pragma unroll
    for (int i = 0; i < 16; i++) {
        v[i] = p[lane + 32 * i];
        s += v[i]; s2 += v[i] * v[i];
    }
    #pragma unroll
    for (int o = 16; o; o >>= 1) {
        s  += __shfl_xor_sync(~0u, s,  o);
        s2 += __shfl_xor_sync(~0u, s2, o);
    }
    float mean = s * (1.f / 512.f);
    float var  = s2 * (1.f / 512.f) - mean * mean;
    float rstd = rsqrtf(var + 1e-5f);
    float* q = out + (size_t)row * 512;
    #pragma unroll
    for (int i = 0; i < 16; i++) {
        int d = lane + 32 * i;
        q[d] = (v[i] - mean) * rstd * g[d] + bb[d];
    }
}

// ---------------- tiled transposes -------------------------------------------
__global__ void transpose_in_kernel(const float* __restrict__ in, float* __restrict__ out) {
    __shared__ float tile[32][33];
    int tx = threadIdx.x, ty = threadIdx.y;
    int t0 = blockIdx.x * 32, b0 = blockIdx.y * 32, k = blockIdx.z;
    #pragma unroll
    for (int i = 0; i < 4; i++)
        tile[ty + 8 * i][tx] = in[(size_t)(b0 + ty + 8 * i) * 12800 + k * 512 + t0 + tx];
    __syncthreads();
    #pragma unroll
    for (int i = 0; i < 4; i++)
        out[(size_t)(t0 + ty + 8 * i) * 3200 + k * 128 + b0 + tx] = tile[tx][ty + 8 * i];
}
__global__ void transpose_out_kernel(const float* __restrict__ in, float* __restrict__ out) {
    __shared__ float tile[32][33];
    int tx = threadIdx.x, ty = threadIdx.y;
    int c0 = blockIdx.x * 32, b0 = blockIdx.y * 32, l = blockIdx.z;
    #pragma unroll
    for (int i = 0; i < 4; i++)
        tile[ty + 8 * i][tx] = in[(size_t)(c0 + ty + 8 * i) * 3200 + l * 128 + b0 + tx];
    __syncthreads();
    #pragma unroll
    for (int i = 0; i < 4; i++)
        out[(size_t)((b0 + ty + 8 * i) * 25 + l) * 512 + c0 + tx] = tile[tx][ty + 8 * i];
}

__global__ void zero_flags_kernel() {
    int i = blockIdx.x * 256 + threadIdx.x;
    if (i < 33 * 4 * 32) g_flags[i] = 0;
}

DEVF void spinwait(const int* p, int need) {
    int v;
    do {
        asm volatile("ld.acquire.gpu.global.b32 %0, [%1];" : "=r"(v) : "l"(p) : "memory");
    } while (v < need);
}

// ---------------- tensor-core LSTM wavefront, 16 compute warps ---------------
#define BROWS 56
#define BSTR  40
__global__ void __launch_bounds__(544, 1) lstm_wave_kernel(
    const float* __restrict__ Wih, const float* __restrict__ Whh,
    const float* __restrict__ bih, const float* __restrict__ bhh)
{
    __shared__ __align__(16) unsigned Bsm[4][BROWS][BSTR];

    int layer = blockIdx.x & 31;
    int chunk = blockIdx.x >> 5;
    int b0 = chunk * 32;
    const float* in  = g_Y + (size_t)layer * YSTRIDE;
    float* outp      = g_Y + (size_t)(layer + 1) * YSTRIDE;
    const int* inflag = g_flags + (layer * 4 + chunk) * 32;
    int* outflag      = g_flags + ((layer + 1) * 4 + chunk) * 32;

    int tid = threadIdx.x;
    int warp = tid >> 5, lane = tid & 31;
    int g = lane >> 2, tg = lane & 3;

    for (int i = tid; i < 4 * BROWS * BSTR; i += 544) ((unsigned*)Bsm)[i] = 0;

    bool isComp = (warp < 16);
    int pair = warp & 3;
    int nf   = warp >> 2;
    int u = pair * 8 + g;
    bool valid = isComp && (u < 25);

    unsigned afr[2][7][4];
    float bias_i = 0.f, bias_f = 0.f, bias_g = 0.f, bias_o = 0.f;
    if (isComp) {
        const float* WI = Wih + (size_t)layer * 2500;
        const float* WH = Whh + (size_t)layer * 2500;
        #pragma unroll
        for (int T = 0; T < 2; T++) {
            int rowA = (T == 0 ? 0 : 50) + u;
            int rowB = (T == 0 ? 25 : 75) + u;
            #pragma unroll
            for (int ks = 0; ks < 7; ks++) {
                #pragma unroll
                for (int q = 0; q < 4; q++) {
                    int k = ks * 8 + tg + (q >= 2 ? 4 : 0);
                    int row = (q & 1) ? rowB : rowA;
                    float w = 0.f;
                    if (valid) {
                        if (k < 25)      w = WI[row * 25 + k];
                        else if (k < 50) w = WH[row * 25 + (k - 25)];
                    }
                    afr[T][ks][q] = totf(w);
                }
            }
        }
        if (valid) {
            bias_i = bih[layer * 100 + u]      + bhh[layer * 100 + u];
            bias_f = bih[layer * 100 + 25 + u] + bhh[layer * 100 + 25 + u];
            bias_g = bih[layer * 100 + 50 + u] + bhh[layer * 100 + 50 + u];
            bias_o = bih[layer * 100 + 75 + u] + bhh[layer * 100 + 75 + u];
        }
    }
    float c0s = 0.f, c1s = 0.f;
    __syncthreads();

    unsigned bsmb = (unsigned)__cvta_generic_to_shared(&Bsm[0][0][0]);

    if (warp == 16) {
        if (layer > 0 && lane == 0) spinwait(inflag, 2);
        __syncwarp();
        #pragma unroll
        for (int p = 0; p < 2; p++) {
            const float* src = in + (size_t)p * 3200 + b0;
            #pragma unroll
            for (int k = 0; k < 25; k++)
                Bsm[p][k][lane] = __float_as_uint(src[k * 128 + lane]);
        }
    }
    __syncthreads();

    int cached = 2;
    for (int t = 0; t < 512; t++) {
        int s = t & 3;
        if (isComp) {
            float acc0[4], acc1[4];
            acc0[0] = bias_i; acc0[1] = bias_i;
            acc0[2] = bias_f; acc0[3] = bias_f;
            acc1[0] = bias_g; acc1[1] = bias_g;
            acc1[2] = bias_o; acc1[3] = bias_o;
            const unsigned* Bp = &Bsm[s][0][0];
            #pragma unroll
            for (int ks = 0; ks < 7; ks++) {
                int r0 = (ks * 8 + tg) * BSTR;
                unsigned b0v = Bp[r0 + nf * 8 + g];
                unsigned b1v = Bp[r0 + 4 * BSTR + nf * 8 + g];
                mma_tf32(acc0, afr[0][ks], b0v, b1v);
                mma_tf32(acc1, afr[1][ks], b0v, b1v);
            }
            unsigned* Bn = &Bsm[(t + 1) & 3][0][0];
            float i0 = sig_fast(acc0[0]),  i1 = sig_fast(acc0[1]);
            float f0 = sig_fast(acc0[2]),  f1 = sig_fast(acc0[3]);
            float q0 = tanh_fast(acc1[0]), q1 = tanh_fast(acc1[1]);
            float o0 = sig_fast(acc1[2]),  o1 = sig_fast(acc1[3]);
            c0s = f0 * c0s + i0 * q0;
            c1s = f1 * c1s + i1 * q1;
            float h0 = o0 * tanh_fast(c0s);
            float h1 = o1 * tanh_fast(c1s);
            if (valid) {
                uint2 hp = make_uint2(__float_as_uint(h0), __float_as_uint(h1));
                *(uint2*)&Bn[(25 + u) * BSTR + nf * 8 + 2 * tg] = hp;
                *(float2*)(outp + (size_t)t * 3200 + u * 128 + b0 + nf * 8 + 2 * tg)
                    = make_float2(h0, h1);
            }
        } else {
            if (t < 510) {
                if (layer > 0 && lane == 0) {
                    int need = t + 3;
                    if (cached < need) {
                        int v;
                        do {
                            asm volatile("ld.acquire.gpu.global.b32 %0, [%1];" : "=r"(v) : "l"(inflag) : "memory");
                        } while (v < need);
                        cached = v;
                    }
                }
                __syncwarp();
                const float* src = in + (size_t)(t + 2) * 3200 + b0 + lane;
                unsigned dst = bsmb + ((((t + 2) & 3) * BROWS) * BSTR + lane) * 4;
                #pragma unroll
                for (int k = 0; k < 25; k++)
                    cpasync4(dst + k * BSTR * 4, src + k * 128);
                cp_commit();
                cp_wait1();
            } else {
                cp_wait0();
            }
        }
        __syncthreads();
        if (tid == 0) {
            int nv = t + 1;
            asm volatile("st.release.gpu.global.b32 [%0], %1;" :: "l"(outflag), "r"(nv) : "memory");
        }
    }
}

// ---------------- launcher ---------------------------------------------------
extern "C" void kernel_launch(void* const* d_in, const int* in_sizes, int n_in,
                              void* d_out, int out_size)
{
    const float* x     = (const float*)d_in[0];
    const float* cross = (const float*)d_in[1];
    const float* Wq_s = (const float*)d_in[2];  const float* bq_s = (const float*)d_in[3];
    const float* Wk_s = (const float*)d_in[4];  const float* bk_s = (const float*)d_in[5];
    const float* Wv_s = (const float*)d_in[6];  const float* bv_s = (const float*)d_in[7];
    const float* Wo_s = (const float*)d_in[8];  const float* bo_s = (const float*)d_in[9];
    const float* Wq_c = (const float*)d_in[10]; const float* bq_c = (const float*)d_in[11];
    const float* Wk_c = (const float*)d_in[12]; const float* bk_c = (const float*)d_in[13];
    const float* Wv_c = (const float*)d_in[14]; const float* bv_c = (const float*)d_in[15];
    const float* Wo_c = (const float*)d_in[16]; const float* bo_c = (const float*)d_in[17];
    const float* g1 = (const float*)d_in[18]; const float* b1 = (const float*)d_in[19];
    const float* g2 = (const float*)d_in[20]; const float* b2 = (const float*)d_in[21];
    const float* g3 = (const float*)d_in[22]; const float* b3 = (const float*)d_in[23];
    const float* W_ih = (const float*)d_in[24];
    const float* W_hh = (const float*)d_in[25];
    const float* b_ih = (const float*)d_in[26];
    const float* b_hh = (const float*)d_in[27];
    const float* Wc = (const float*)d_in[28]; const float* bc = (const float*)d_in[29];
    float* out = (float*)d_out;

    float *gq, *gk, *gv, *gkc, *gvc, *gctx, *gx1, *gx2, *gtmp, *gyt, *gY;
    cudaGetSymbolAddress((void**)&gq,   g_q);
    cudaGetSymbolAddress((void**)&gk,   g_k);
    cudaGetSymbolAddress((void**)&gv,   g_v);
    cudaGetSymbolAddress((void**)&gkc,  g_kc);
    cudaGetSymbolAddress((void**)&gvc,  g_vc);
    cudaGetSymbolAddress((void**)&gctx, g_ctx);
    cudaGetSymbolAddress((void**)&gx1,  g_x1);
    cudaGetSymbolAddress((void**)&gx2,  g_x2);
    cudaGetSymbolAddress((void**)&gtmp, g_tmp);
    cudaGetSymbolAddress((void**)&gyt,  g_yt);
    cudaGetSymbolAddress((void**)&gY,   g_Y);

    const int M1 = 3200;    // B*L
    zero_flags_kernel<<<17, 256>>>();

    // ---- merged: self QKV (from x) + cross KV (from cross) ----
    {
        Gemm5 s;
        s.A[0] = x;     s.W[0] = Wq_s; s.bias[0] = bq_s; s.C[0] = gq;  s.M[0] = 3200;
        s.A[1] = x;     s.W[1] = Wk_s; s.bias[1] = bk_s; s.C[1] = gk;  s.M[1] = 3200;
        s.A[2] = x;     s.W[2] = Wv_s; s.bias[2] = bv_s; s.C[2] = gv;  s.M[2] = 3200;
        s.A[3] = cross; s.W[3] = Wk_c; s.bias[3] = bk_c; s.C[3] = gkc; s.M[3] = 12288;
        s.A[4] = cross; s.W[4] = Wv_c; s.bias[4] = bv_c; s.C[4] = gvc; s.M[4] = 12288;
        gemm128_kernel<<<dim3(96, 4, 5), 256>>>(s);
    }
    attn_kernel<25><<<128 * 8, 256>>>(gq, gk, gv, gctx);
    {
        GemmSet s = {{Wo_s, nullptr, nullptr}, {bo_s, nullptr, nullptr},
                     {x, nullptr, nullptr}, {gtmp, nullptr, nullptr}};
        gemm_tc_kernel<false><<<dim3(50, 8, 1), 128>>>(gctx, s);
    }
    ln_kernel<<<M1 / 8, 256>>>(gtmp, g1, b1, gx1, M1);

    // ---- cross attention (KV already computed) ----
    {
        GemmSet s = {{Wq_c, nullptr, nullptr}, {bq_c, nullptr, nullptr},
                     {nullptr, nullptr, nullptr}, {gq, nullptr, nullptr}};
        gemm_tc_kernel<false><<<dim3(50, 8, 1), 128>>>(gx1, s);
    }
    attn_kernel<96><<<128 * 8, 256>>>(gq, gkc, gvc, gctx);
    {
        GemmSet s = {{Wo_c, nullptr, nullptr}, {bo_c, nullptr, nullptr},
                     {gx1, nullptr, nullptr}, {gtmp, nullptr, nullptr}};
        gemm_tc_kernel<false><<<dim3(50, 8, 1), 128>>>(gctx, s);
    }
    ln_kernel<<<M1 / 8, 256>>>(gtmp, g2, b2, gx2, M1);

    // ---- LSTM wavefront over feature axis ----
    transpose_in_kernel<<<dim3(16, 4, 25), dim3(32, 8)>>>(gx2, gY);
    lstm_wave_kernel<<<128, 544>>>(W_ih, W_hh, b_ih, b_hh);

    // ---- pointwise conv + residual + final LN ----
    transpose_out_kernel<<<dim3(16, 4, 25), dim3(32, 8)>>>(gY + 32ull * YSTRIDE, gyt);
    {
        GemmSet s = {{Wc, nullptr, nullptr}, {bc, nullptr, nullptr},
                     {gx2, nullptr, nullptr}, {gtmp, nullptr, nullptr}};
        gemm_tc_kernel<true><<<dim3(50, 8, 1), 128>>>(gyt, s);
    }
    ln_kernel<<<M1 / 8, 256>>>(gtmp, g3, b3, out, M1);
}